// round 12
// baseline (speedup 1.0000x reference)
#include <cuda_runtime.h>
#include <cuda_fp16.h>
#include <math.h>
#include <stdint.h>

#define T_STEPS 512
#define BATCH   64
#define DIM     1024
#define HID     1024
#define N4      4096                 // 4 * HID
#define M_TOT   (T_STEPS * BATCH)    // 32768
#define NBLK    128                  // persistent blocks (<=148 SMs, 1/SM)

// ---------------- scratch (static device globals; no runtime allocation) ----
__device__ float g_Xp[(size_t)M_TOT * N4];   // 512 MB: X @ Wx + b, [T*B, 4H]
__device__ float g_C[BATCH * HID];           // cell state
__device__ uint32_t g_Hh[BATCH * HID / 2];   // H(t) as packed half2 [row][k/2]
__device__ unsigned int g_slots[NBLK];       // per-block barrier slots

// ---------------- init: cell state, H0 half2 staging, barrier slots ----------
__global__ void init_c_kernel(const float* __restrict__ C0,
                              const float* __restrict__ H0) {
    int i = blockIdx.x * 256 + threadIdx.x;
    if (i < BATCH * HID) g_C[i] = C0[i];
    if (i < BATCH * HID / 2) {
        __half2 h = __floats2half2_rn(H0[2 * i], H0[2 * i + 1]);
        g_Hh[i] = *(uint32_t*)&h;
    }
    if (i < NBLK) g_slots[i] = 0u;
}

// ---------------- helpers ----------------------------------------------------
__device__ __forceinline__ uint32_t cvt_tf32(float x) {
    uint32_t r;
    asm("cvt.rna.tf32.f32 %0, %1;" : "=r"(r) : "f"(x));
    return r;
}

__device__ __forceinline__ uint32_t pack_h2(float lo, float hi) {
    __half2 h = __floats2half2_rn(lo, hi);
    return *(uint32_t*)&h;
}

__device__ __forceinline__ void mma_tf32(float& c0, float& c1, float& c2, float& c3,
                                         uint32_t a0, uint32_t a1, uint32_t a2, uint32_t a3,
                                         uint32_t b0, uint32_t b1) {
    asm volatile(
        "mma.sync.aligned.m16n8k8.row.col.f32.tf32.tf32.f32 "
        "{%0,%1,%2,%3}, {%4,%5,%6,%7}, {%8,%9}, {%0,%1,%2,%3};\n"
        : "+f"(c0), "+f"(c1), "+f"(c2), "+f"(c3)
        : "r"(a0), "r"(a1), "r"(a2), "r"(a3), "r"(b0), "r"(b1));
}

__device__ __forceinline__ void mma_f16(float& c0, float& c1, float& c2, float& c3,
                                        uint32_t a0, uint32_t a1, uint32_t a2, uint32_t a3,
                                        uint32_t b0, uint32_t b1) {
    asm volatile(
        "mma.sync.aligned.m16n8k16.row.col.f32.f16.f16.f32 "
        "{%0,%1,%2,%3}, {%4,%5,%6,%7}, {%8,%9}, {%0,%1,%2,%3};\n"
        : "+f"(c0), "+f"(c1), "+f"(c2), "+f"(c3)
        : "r"(a0), "r"(a1), "r"(a2), "r"(a3), "r"(b0), "r"(b1));
}

__device__ __forceinline__ unsigned slot_ld_acquire(const unsigned* p) {
    unsigned v;
    asm volatile("ld.global.acquire.gpu.u32 %0, [%1];" : "=r"(v) : "l"(p) : "memory");
    return v;
}
__device__ __forceinline__ void slot_st_release(unsigned* p, unsigned v) {
    asm volatile("st.global.release.gpu.u32 [%0], %1;" :: "l"(p), "r"(v) : "memory");
}
__device__ __forceinline__ void fence_acq_rel_gpu() {
    asm volatile("fence.acq_rel.gpu;" ::: "memory");
}

// ---------------- big GEMM (tf32 tensor cores): g_Xp = X @ Wx + b ------------
__global__ __launch_bounds__(256)
void xproj_tf32_kernel(const float* __restrict__ X,
                       const float* __restrict__ W0, const float* __restrict__ W1,
                       const float* __restrict__ W2, const float* __restrict__ W3,
                       const float* __restrict__ b0, const float* __restrict__ b1,
                       const float* __restrict__ b2, const float* __restrict__ b3) {
    const int bn = blockIdx.x * 128;
    const int bm = blockIdx.y * 128;
    const int gate = bn >> 10;
    const float* W  = (gate == 0) ? W0 : (gate == 1) ? W1 : (gate == 2) ? W2 : W3;
    const float* bb = (gate == 0) ? b0 : (gate == 1) ? b1 : (gate == 2) ? b2 : b3;
    const int col0 = bn & (HID - 1);

    __shared__ uint32_t As[2][16][136];
    __shared__ uint32_t Bs[2][16][136];

    const int tid  = threadIdx.x;
    const int lane = tid & 31;
    const int warp = tid >> 5;
    const int wm   = warp >> 2;
    const int wn   = warp & 3;
    const int qg   = lane >> 2;
    const int qk   = lane & 3;

    const int ar  = tid >> 1;
    const int ac  = (tid & 1) * 8;
    const int br  = tid >> 4;
    const int bcn = tid & 15;

    float c[4][4][4];
    #pragma unroll
    for (int mt = 0; mt < 4; mt++)
        #pragma unroll
        for (int nt = 0; nt < 4; nt++)
            #pragma unroll
            for (int r = 0; r < 4; r++) c[mt][nt][r] = 0.0f;

    {
        float4 av0 = *(const float4*)&X[(size_t)(bm + ar) * DIM + ac];
        float4 av1 = *(const float4*)&X[(size_t)(bm + ar) * DIM + ac + 4];
        As[0][ac + 0][ar] = cvt_tf32(av0.x); As[0][ac + 1][ar] = cvt_tf32(av0.y);
        As[0][ac + 2][ar] = cvt_tf32(av0.z); As[0][ac + 3][ar] = cvt_tf32(av0.w);
        As[0][ac + 4][ar] = cvt_tf32(av1.x); As[0][ac + 5][ar] = cvt_tf32(av1.y);
        As[0][ac + 6][ar] = cvt_tf32(av1.z); As[0][ac + 7][ar] = cvt_tf32(av1.w);
        #pragma unroll
        for (int j = 0; j < 8; j++)
            Bs[0][br][bcn + 16 * j] =
                cvt_tf32(W[(size_t)br * HID + col0 + bcn + 16 * j]);
    }
    __syncthreads();

    int buf = 0;
    for (int kt = 0; kt < DIM / 16; kt++) {
        float4 av0, av1;
        float bvr[8];
        const int k0n = (kt + 1) * 16;
        const bool has_next = (kt + 1 < DIM / 16);
        if (has_next) {
            av0 = *(const float4*)&X[(size_t)(bm + ar) * DIM + k0n + ac];
            av1 = *(const float4*)&X[(size_t)(bm + ar) * DIM + k0n + ac + 4];
            #pragma unroll
            for (int j = 0; j < 8; j++)
                bvr[j] = W[(size_t)(k0n + br) * HID + col0 + bcn + 16 * j];
        }

        #pragma unroll
        for (int k8 = 0; k8 < 16; k8 += 8) {
            uint32_t af[4][4];
            #pragma unroll
            for (int mt = 0; mt < 4; mt++) {
                const int m = wm * 64 + mt * 16 + qg;
                af[mt][0] = As[buf][k8 + qk][m];
                af[mt][1] = As[buf][k8 + qk][m + 8];
                af[mt][2] = As[buf][k8 + 4 + qk][m];
                af[mt][3] = As[buf][k8 + 4 + qk][m + 8];
            }
            uint32_t bf[4][2];
            #pragma unroll
            for (int nt = 0; nt < 4; nt++) {
                const int n = wn * 32 + nt * 8 + qg;
                bf[nt][0] = Bs[buf][k8 + qk][n];
                bf[nt][1] = Bs[buf][k8 + 4 + qk][n];
            }
            #pragma unroll
            for (int mt = 0; mt < 4; mt++)
                #pragma unroll
                for (int nt = 0; nt < 4; nt++)
                    mma_tf32(c[mt][nt][0], c[mt][nt][1], c[mt][nt][2], c[mt][nt][3],
                             af[mt][0], af[mt][1], af[mt][2], af[mt][3],
                             bf[nt][0], bf[nt][1]);
        }

        if (has_next) {
            const int nb = buf ^ 1;
            As[nb][ac + 0][ar] = cvt_tf32(av0.x); As[nb][ac + 1][ar] = cvt_tf32(av0.y);
            As[nb][ac + 2][ar] = cvt_tf32(av0.z); As[nb][ac + 3][ar] = cvt_tf32(av0.w);
            As[nb][ac + 4][ar] = cvt_tf32(av1.x); As[nb][ac + 5][ar] = cvt_tf32(av1.y);
            As[nb][ac + 6][ar] = cvt_tf32(av1.z); As[nb][ac + 7][ar] = cvt_tf32(av1.w);
            #pragma unroll
            for (int j = 0; j < 8; j++)
                Bs[nb][br][bcn + 16 * j] = cvt_tf32(bvr[j]);
            __syncthreads();
            buf = nb;
        }
    }

    #pragma unroll
    for (int mt = 0; mt < 4; mt++) {
        #pragma unroll
        for (int nt = 0; nt < 4; nt++) {
            const int colg = wn * 32 + nt * 8 + 2 * qk;
            const float bx0 = bb[col0 + colg];
            const float bx1 = bb[col0 + colg + 1];
            const size_t row0 = (size_t)(bm + wm * 64 + mt * 16 + qg);
            float2 v0 = make_float2(c[mt][nt][0] + bx0, c[mt][nt][1] + bx1);
            float2 v1 = make_float2(c[mt][nt][2] + bx0, c[mt][nt][3] + bx1);
            *(float2*)&g_Xp[row0 * N4 + bn + colg]       = v0;
            *(float2*)&g_Xp[(row0 + 8) * N4 + bn + colg] = v1;
        }
    }
}

// ---------------- persistent recurrence kernel (fp16 m16n8k16) ---------------
// 128 blocks x 256 threads (8 warps), 1 block/SM. Block owns hidden cols
// [8*bid, 8*bid+8) x 4 gates x 64 batch rows. K split 2-way across warp
// groups. Wh resident in smem as half2 pairs; H handed off between steps as
// packed half2 in g_Hh (loads need no conversion). K-tile = 64 (8 tiles,
// 1 sync each). Per-block slot barrier (no atomic contention).
//
// Wp[kc16=64][qk=4][gc pad 35][slot 2]  (half2 words) : 71,680 B
// As[kg=2][buf=2][m=64][pos 32 pad 36]  (half2 words) : 73,728 B
// sg[kg=2][row=64][gc pad 33]           (float)       : 16,896 B
#define WP_WORDS (64 * 4 * 35 * 2)
#define AS_WORDS (2 * 2 * 64 * 36)
#define SG_WORDS (2 * 64 * 33)
#define SMEM_BYTES ((WP_WORDS + AS_WORDS + SG_WORDS) * 4)

__global__ __launch_bounds__(256)
void lstm_persistent(const float* __restrict__ W0, const float* __restrict__ W1,
                     const float* __restrict__ W2, const float* __restrict__ W3,
                     float* __restrict__ out) {
    extern __shared__ unsigned char smem_raw[];
    uint32_t (*Wp)[4][35][2]  = (uint32_t (*)[4][35][2])smem_raw;
    uint32_t (*As)[2][64][36] = (uint32_t (*)[2][64][36])(smem_raw + WP_WORDS * 4);
    float    (*sg)[64][33]    = (float (*)[64][33])(smem_raw + (WP_WORDS + AS_WORDS) * 4);

    const int tid  = threadIdx.x;
    const int lane = tid & 31;
    const int warp = tid >> 5;           // 0..7
    const int colbase = blockIdx.x * 8;

    const float* Wg[4] = {W0, W1, W2, W3};

    const int kg = warp >> 2;            // K-group 0/1
    const int wq = warp & 3;
    const int wm = wq >> 1;              // rows 32*wm
    const int wn = wq & 1;               // gate-cols 16*wn
    const int qg = lane >> 2;
    const int qk = lane & 3;

    // H loader mapping (128 threads per K-group), K-tile = 64 (32 half2)
    const int gtid = tid & 127;
    const int k16 = gtid & 15;           // half2 lane within half-tile
    const int rh  = gtid >> 4;           // rows rh + 8i
    // store position within tile for half2 index kh (0..31):
    //   ch = kh>>3 (chunk of K=16), within = kh&7, pos = ch*8 + ((w&3)<<1 | w>>2)
    const int posA = ((k16 >> 3) << 3) | ((k16 & 3) << 1) | ((k16 >> 2) & 1);          // kh=k16
    const int posB = (((k16 + 16) >> 3) << 3) | ((k16 & 3) << 1) | ((k16 >> 2) & 1);   // kh=k16+16

    // epilogue mapping: 2 adjacent cells per thread
    const int erow = tid >> 2;           // 0..63
    const int ecc  = (tid & 3) * 2;      // 0,2,4,6

    // ---- load resident W (once) as half2 pairs ----
    {
        const int gc  = tid & 31;
        const int g   = gc >> 3;
        const int cl  = gc & 7;
        const int khb = (tid >> 5) * 64;     // each warp covers 64 half2 k-rows
        for (int j = 0; j < 64; j++) {
            const int kh = khb + j;          // 0..511
            const int k  = kh * 2;
            const float lo = Wg[g][(size_t)k * HID + colbase + cl];
            const float hi = Wg[g][(size_t)(k + 1) * HID + colbase + cl];
            const int kc16 = kh >> 3;
            const int win  = kh & 7;
            Wp[kc16][win & 3][gc][win >> 2] = pack_h2(lo, hi);
        }
    }
    __syncthreads();

    for (int t = 0; t < T_STEPS; t++) {
        const float* Xp_t = g_Xp + (size_t)t * BATCH * N4;
        float* Hout = out + (size_t)t * BATCH * HID;

        // ---- prefetch Xp for the epilogue (DRAM latency overlaps the GEMM) ----
        float2 xp[4];
        {
            const size_t xb = (size_t)erow * N4 + colbase + ecc;
            #pragma unroll
            for (int g = 0; g < 4; g++)
                xp[g] = *(const float2*)&Xp_t[xb + (size_t)g * HID];
        }

        float c[2][2][4];
        #pragma unroll
        for (int mt = 0; mt < 2; mt++)
            #pragma unroll
            for (int nt = 0; nt < 2; nt++)
                #pragma unroll
                for (int r = 0; r < 4; r++) c[mt][nt][r] = 0.0f;

        const int khbase = kg * 256;     // this half's half2-K origin

        // preload H k-tile 0 (uint32 half2 direct from g_Hh)
        #pragma unroll
        for (int i = 0; i < 8; i++) {
            const int row = rh + 8 * i;
            As[kg][0][row][posA] = __ldcg(&g_Hh[row * 512 + khbase + k16]);
            As[kg][0][row][posB] = __ldcg(&g_Hh[row * 512 + khbase + k16 + 16]);
        }
        __syncthreads();

        int buf = 0;
        for (int kt = 0; kt < 8; kt++) {
            uint32_t hreg[16];
            const bool has_next = (kt + 1 < 8);
            if (has_next) {
                const int kh0 = khbase + (kt + 1) * 32;
                #pragma unroll
                for (int i = 0; i < 8; i++) {
                    const int row = rh + 8 * i;
                    hreg[i]     = __ldcg(&g_Hh[row * 512 + kh0 + k16]);
                    hreg[i + 8] = __ldcg(&g_Hh[row * 512 + kh0 + k16 + 16]);
                }
            }

            // compute on buf: 4 chunks of K=16
            #pragma unroll
            for (int ch = 0; ch < 4; ch++) {
                const int kc16 = kg * 32 + kt * 4 + ch;
                uint2 a01[2], a23[2];
                #pragma unroll
                for (int mt = 0; mt < 2; mt++) {
                    const int m = 32 * wm + 16 * mt;
                    a01[mt] = *(const uint2*)&As[kg][buf][m + qg][ch * 8 + 2 * qk];
                    a23[mt] = *(const uint2*)&As[kg][buf][m + qg + 8][ch * 8 + 2 * qk];
                }
                uint2 bp[2];
                #pragma unroll
                for (int nt = 0; nt < 2; nt++) {
                    const int n = 16 * wn + 8 * nt;
                    bp[nt] = *(const uint2*)&Wp[kc16][qk][n + qg][0];
                }
                #pragma unroll
                for (int mt = 0; mt < 2; mt++)
                    #pragma unroll
                    for (int nt = 0; nt < 2; nt++)
                        mma_f16(c[mt][nt][0], c[mt][nt][1], c[mt][nt][2], c[mt][nt][3],
                                a01[mt].x, a23[mt].x, a01[mt].y, a23[mt].y,
                                bp[nt].x, bp[nt].y);
            }

            if (has_next) {
                const int nb = buf ^ 1;
                // nb's last readers passed the sync that closed tile kt-1.
                #pragma unroll
                for (int i = 0; i < 8; i++) {
                    const int row = rh + 8 * i;
                    As[kg][nb][row][posA] = hreg[i];
                    As[kg][nb][row][posB] = hreg[i + 8];
                }
                __syncthreads();
                buf = nb;
            }
        }

        // stash per-K-group gate partials
        #pragma unroll
        for (int mt = 0; mt < 2; mt++) {
            #pragma unroll
            for (int nt = 0; nt < 2; nt++) {
                const int row = 32 * wm + 16 * mt + qg;
                const int cn  = 16 * wn + 8 * nt + 2 * qk;
                sg[kg][row][cn]         = c[mt][nt][0];
                sg[kg][row][cn + 1]     = c[mt][nt][1];
                sg[kg][row + 8][cn]     = c[mt][nt][2];
                sg[kg][row + 8][cn + 1] = c[mt][nt][3];
            }
        }
        __syncthreads();

        // ---- fused LSTM cell epilogue: 2 adjacent cells per thread ----
        {
            const int idx = erow * HID + colbase + ecc;
            float2 cprev = *(const float2*)&g_C[idx];
            float hv[2], cv[2];
            #pragma unroll
            for (int s = 0; s < 2; s++) {
                const int cc = ecc + s;
                float gi = sg[0][erow][0  + cc] + sg[1][erow][0  + cc] + (s ? xp[0].y : xp[0].x);
                float gf = sg[0][erow][8  + cc] + sg[1][erow][8  + cc] + (s ? xp[1].y : xp[1].x);
                float go = sg[0][erow][16 + cc] + sg[1][erow][16 + cc] + (s ? xp[2].y : xp[2].x);
                float gg = sg[0][erow][24 + cc] + sg[1][erow][24 + cc] + (s ? xp[3].y : xp[3].x);

                float I = 1.0f / (1.0f + __expf(-gi));
                float F = 1.0f / (1.0f + __expf(-gf));
                float O = 1.0f / (1.0f + __expf(-go));
                float G = tanhf(gg);

                cv[s] = fmaf(F, (s ? cprev.y : cprev.x), I * G);
                hv[s] = O * tanhf(cv[s]);
            }
            *(float2*)&g_C[idx] = make_float2(cv[0], cv[1]);
            __stcg((float2*)&Hout[idx], make_float2(hv[0], hv[1]));
            __stcg(&g_Hh[erow * 512 + ((colbase + ecc) >> 1)], pack_h2(hv[0], hv[1]));
        }

        // ---- slot barrier: release own slot, acquire-poll all slots ----
        __threadfence();
        __syncthreads();
        if (tid == 0)
            slot_st_release(&g_slots[blockIdx.x], (unsigned)(t + 1));
        if (tid < NBLK) {
            while (slot_ld_acquire(&g_slots[tid]) < (unsigned)(t + 1)) {}
        }
        __syncthreads();
        fence_acq_rel_gpu();
    }
}

// ---------------- tail: H_f and C_f after outputs ---------------------------
__global__ void finalize_kernel(float* __restrict__ out) {
    int i = blockIdx.x * 256 + threadIdx.x;
    if (i < BATCH * HID) {
        size_t base = (size_t)T_STEPS * BATCH * HID;
        out[base + i] = out[(size_t)(T_STEPS - 1) * BATCH * HID + i];  // H_f
        out[base + BATCH * HID + i] = g_C[i];                          // C_f
    }
}

// ---------------- launch -----------------------------------------------------
extern "C" void kernel_launch(void* const* d_in, const int* in_sizes, int n_in,
                              void* d_out, int out_size) {
    const float* X   = (const float*)d_in[0];
    const float* H0  = (const float*)d_in[1];
    const float* C0  = (const float*)d_in[2];
    const float* Wxi = (const float*)d_in[3];
    const float* Wxf = (const float*)d_in[4];
    const float* Wxo = (const float*)d_in[5];
    const float* Wxc = (const float*)d_in[6];
    const float* Whi = (const float*)d_in[7];
    const float* Whf = (const float*)d_in[8];
    const float* Who = (const float*)d_in[9];
    const float* Whc = (const float*)d_in[10];
    const float* bi  = (const float*)d_in[11];
    const float* bf  = (const float*)d_in[12];
    const float* bo  = (const float*)d_in[13];
    const float* bc  = (const float*)d_in[14];
    float* out = (float*)d_out;

    cudaFuncSetAttribute(lstm_persistent,
                         cudaFuncAttributeMaxDynamicSharedMemorySize, SMEM_BYTES);

    init_c_kernel<<<256, 256>>>(C0, H0);
    xproj_tf32_kernel<<<dim3(32, 256), 256>>>(X, Wxi, Wxf, Wxo, Wxc,
                                              bi, bf, bo, bc);
    lstm_persistent<<<NBLK, 256, SMEM_BYTES>>>(Whi, Whf, Who, Whc, out);
    finalize_kernel<<<256, 256>>>(out);
}

// round 13
// speedup vs baseline: 1.4111x; 1.4111x over previous
#include <cuda_runtime.h>
#include <cuda_fp16.h>
#include <math.h>
#include <stdint.h>

#define T_STEPS 512
#define BATCH   64
#define DIM     1024
#define HID     1024
#define N4      4096                 // 4 * HID
#define M_TOT   (T_STEPS * BATCH)    // 32768
#define NBLK    128                  // persistent blocks (<=148 SMs, 1/SM)

// ---------------- scratch (static device globals; no runtime allocation) ----
__device__ float g_Xp[(size_t)M_TOT * N4];   // 512 MB: X @ Wx + b, [T*B, 4H]
__device__ float g_C[BATCH * HID];           // cell state
__device__ uint32_t g_Hh[BATCH * HID / 2];   // H(t) as packed half2 [row][k/2]
__device__ unsigned int g_bar;               // software grid barrier counter

// ---------------- init: cell state, H0 half2 staging, barrier ----------------
__global__ void init_c_kernel(const float* __restrict__ C0,
                              const float* __restrict__ H0) {
    int i = blockIdx.x * 256 + threadIdx.x;
    if (i < BATCH * HID) g_C[i] = C0[i];
    if (i < BATCH * HID / 2) {
        __half2 h = __floats2half2_rn(H0[2 * i], H0[2 * i + 1]);
        g_Hh[i] = *(uint32_t*)&h;
    }
    if (i == 0) g_bar = 0u;
}

// ---------------- helpers ----------------------------------------------------
__device__ __forceinline__ uint32_t cvt_tf32(float x) {
    uint32_t r;
    asm("cvt.rna.tf32.f32 %0, %1;" : "=r"(r) : "f"(x));
    return r;
}

__device__ __forceinline__ uint32_t pack_h2(float lo, float hi) {
    __half2 h = __floats2half2_rn(lo, hi);
    return *(uint32_t*)&h;
}

__device__ __forceinline__ void mma_tf32(float& c0, float& c1, float& c2, float& c3,
                                         uint32_t a0, uint32_t a1, uint32_t a2, uint32_t a3,
                                         uint32_t b0, uint32_t b1) {
    asm volatile(
        "mma.sync.aligned.m16n8k8.row.col.f32.tf32.tf32.f32 "
        "{%0,%1,%2,%3}, {%4,%5,%6,%7}, {%8,%9}, {%0,%1,%2,%3};\n"
        : "+f"(c0), "+f"(c1), "+f"(c2), "+f"(c3)
        : "r"(a0), "r"(a1), "r"(a2), "r"(a3), "r"(b0), "r"(b1));
}

__device__ __forceinline__ void mma_f16(float& c0, float& c1, float& c2, float& c3,
                                        uint32_t a0, uint32_t a1, uint32_t a2, uint32_t a3,
                                        uint32_t b0, uint32_t b1) {
    asm volatile(
        "mma.sync.aligned.m16n8k16.row.col.f32.f16.f16.f32 "
        "{%0,%1,%2,%3}, {%4,%5,%6,%7}, {%8,%9}, {%0,%1,%2,%3};\n"
        : "+f"(c0), "+f"(c1), "+f"(c2), "+f"(c3)
        : "r"(a0), "r"(a1), "r"(a2), "r"(a3), "r"(b0), "r"(b1));
}

__device__ __forceinline__ unsigned bar_ld_acquire(const unsigned* p) {
    unsigned v;
    asm volatile("ld.global.acquire.gpu.u32 %0, [%1];" : "=r"(v) : "l"(p) : "memory");
    return v;
}
__device__ __forceinline__ void bar_red_release(unsigned* p, unsigned v) {
    asm volatile("red.release.gpu.global.add.u32 [%0], %1;" :: "l"(p), "r"(v) : "memory");
}
__device__ __forceinline__ void fence_acq_rel_gpu() {
    asm volatile("fence.acq_rel.gpu;" ::: "memory");
}

// ---------------- big GEMM (tf32 tensor cores): g_Xp = X @ Wx + b ------------
__global__ __launch_bounds__(256)
void xproj_tf32_kernel(const float* __restrict__ X,
                       const float* __restrict__ W0, const float* __restrict__ W1,
                       const float* __restrict__ W2, const float* __restrict__ W3,
                       const float* __restrict__ b0, const float* __restrict__ b1,
                       const float* __restrict__ b2, const float* __restrict__ b3) {
    const int bn = blockIdx.x * 128;
    const int bm = blockIdx.y * 128;
    const int gate = bn >> 10;
    const float* W  = (gate == 0) ? W0 : (gate == 1) ? W1 : (gate == 2) ? W2 : W3;
    const float* bb = (gate == 0) ? b0 : (gate == 1) ? b1 : (gate == 2) ? b2 : b3;
    const int col0 = bn & (HID - 1);

    __shared__ uint32_t As[2][16][136];
    __shared__ uint32_t Bs[2][16][136];

    const int tid  = threadIdx.x;
    const int lane = tid & 31;
    const int warp = tid >> 5;
    const int wm   = warp >> 2;
    const int wn   = warp & 3;
    const int qg   = lane >> 2;
    const int qk   = lane & 3;

    const int ar  = tid >> 1;
    const int ac  = (tid & 1) * 8;
    const int br  = tid >> 4;
    const int bcn = tid & 15;

    float c[4][4][4];
    #pragma unroll
    for (int mt = 0; mt < 4; mt++)
        #pragma unroll
        for (int nt = 0; nt < 4; nt++)
            #pragma unroll
            for (int r = 0; r < 4; r++) c[mt][nt][r] = 0.0f;

    {
        float4 av0 = *(const float4*)&X[(size_t)(bm + ar) * DIM + ac];
        float4 av1 = *(const float4*)&X[(size_t)(bm + ar) * DIM + ac + 4];
        As[0][ac + 0][ar] = cvt_tf32(av0.x); As[0][ac + 1][ar] = cvt_tf32(av0.y);
        As[0][ac + 2][ar] = cvt_tf32(av0.z); As[0][ac + 3][ar] = cvt_tf32(av0.w);
        As[0][ac + 4][ar] = cvt_tf32(av1.x); As[0][ac + 5][ar] = cvt_tf32(av1.y);
        As[0][ac + 6][ar] = cvt_tf32(av1.z); As[0][ac + 7][ar] = cvt_tf32(av1.w);
        #pragma unroll
        for (int j = 0; j < 8; j++)
            Bs[0][br][bcn + 16 * j] =
                cvt_tf32(W[(size_t)br * HID + col0 + bcn + 16 * j]);
    }
    __syncthreads();

    int buf = 0;
    for (int kt = 0; kt < DIM / 16; kt++) {
        float4 av0, av1;
        float bvr[8];
        const int k0n = (kt + 1) * 16;
        const bool has_next = (kt + 1 < DIM / 16);
        if (has_next) {
            av0 = *(const float4*)&X[(size_t)(bm + ar) * DIM + k0n + ac];
            av1 = *(const float4*)&X[(size_t)(bm + ar) * DIM + k0n + ac + 4];
            #pragma unroll
            for (int j = 0; j < 8; j++)
                bvr[j] = W[(size_t)(k0n + br) * HID + col0 + bcn + 16 * j];
        }

        #pragma unroll
        for (int k8 = 0; k8 < 16; k8 += 8) {
            uint32_t af[4][4];
            #pragma unroll
            for (int mt = 0; mt < 4; mt++) {
                const int m = wm * 64 + mt * 16 + qg;
                af[mt][0] = As[buf][k8 + qk][m];
                af[mt][1] = As[buf][k8 + qk][m + 8];
                af[mt][2] = As[buf][k8 + 4 + qk][m];
                af[mt][3] = As[buf][k8 + 4 + qk][m + 8];
            }
            uint32_t bf[4][2];
            #pragma unroll
            for (int nt = 0; nt < 4; nt++) {
                const int n = wn * 32 + nt * 8 + qg;
                bf[nt][0] = Bs[buf][k8 + qk][n];
                bf[nt][1] = Bs[buf][k8 + 4 + qk][n];
            }
            #pragma unroll
            for (int mt = 0; mt < 4; mt++)
                #pragma unroll
                for (int nt = 0; nt < 4; nt++)
                    mma_tf32(c[mt][nt][0], c[mt][nt][1], c[mt][nt][2], c[mt][nt][3],
                             af[mt][0], af[mt][1], af[mt][2], af[mt][3],
                             bf[nt][0], bf[nt][1]);
        }

        if (has_next) {
            const int nb = buf ^ 1;
            As[nb][ac + 0][ar] = cvt_tf32(av0.x); As[nb][ac + 1][ar] = cvt_tf32(av0.y);
            As[nb][ac + 2][ar] = cvt_tf32(av0.z); As[nb][ac + 3][ar] = cvt_tf32(av0.w);
            As[nb][ac + 4][ar] = cvt_tf32(av1.x); As[nb][ac + 5][ar] = cvt_tf32(av1.y);
            As[nb][ac + 6][ar] = cvt_tf32(av1.z); As[nb][ac + 7][ar] = cvt_tf32(av1.w);
            #pragma unroll
            for (int j = 0; j < 8; j++)
                Bs[nb][br][bcn + 16 * j] = cvt_tf32(bvr[j]);
            __syncthreads();
            buf = nb;
        }
    }

    #pragma unroll
    for (int mt = 0; mt < 4; mt++) {
        #pragma unroll
        for (int nt = 0; nt < 4; nt++) {
            const int colg = wn * 32 + nt * 8 + 2 * qk;
            const float bx0 = bb[col0 + colg];
            const float bx1 = bb[col0 + colg + 1];
            const size_t row0 = (size_t)(bm + wm * 64 + mt * 16 + qg);
            float2 v0 = make_float2(c[mt][nt][0] + bx0, c[mt][nt][1] + bx1);
            float2 v1 = make_float2(c[mt][nt][2] + bx0, c[mt][nt][3] + bx1);
            *(float2*)&g_Xp[row0 * N4 + bn + colg]       = v0;
            *(float2*)&g_Xp[(row0 + 8) * N4 + bn + colg] = v1;
        }
    }
}

// ---------------- persistent recurrence kernel (fp16 m16n8k16) ---------------
// R11 structure exactly (K-tile 32 per K-group, counter barrier), plus:
//  - H handoff as packed half2 via g_Hh (raw u32 A-tile loads, no cvt)
//  - Xp epilogue prefetch at step start (DRAM latency overlaps GEMM)
//
// Wp[kc16=64][qk=4][gc pad 35][slot 2]  (half2 words) : 71,680 B
// As[kg=2][buf=2][m=64][pos pad 18]     (half2 words) : 18,432 B
// sg[kg=2][row=64][gc pad 33]           (float)       : 16,896 B
#define WP_WORDS (64 * 4 * 35 * 2)
#define AS_WORDS (2 * 2 * 64 * 18)
#define SG_WORDS (2 * 64 * 33)
#define SMEM_BYTES ((WP_WORDS + AS_WORDS + SG_WORDS) * 4)

__global__ __launch_bounds__(256)
void lstm_persistent(const float* __restrict__ W0, const float* __restrict__ W1,
                     const float* __restrict__ W2, const float* __restrict__ W3,
                     float* __restrict__ out) {
    extern __shared__ unsigned char smem_raw[];
    uint32_t (*Wp)[4][35][2]  = (uint32_t (*)[4][35][2])smem_raw;
    uint32_t (*As)[2][64][18] = (uint32_t (*)[2][64][18])(smem_raw + WP_WORDS * 4);
    float    (*sg)[64][33]    = (float (*)[64][33])(smem_raw + (WP_WORDS + AS_WORDS) * 4);

    const int tid  = threadIdx.x;
    const int lane = tid & 31;
    const int warp = tid >> 5;           // 0..7
    const int colbase = blockIdx.x * 8;

    const float* Wg[4] = {W0, W1, W2, W3};

    const int kg = warp >> 2;            // K-group 0/1
    const int wq = warp & 3;
    const int wm = wq >> 1;              // rows 32*wm
    const int wn = wq & 1;               // gate-cols 16*wn
    const int qg = lane >> 2;
    const int qk = lane & 3;

    // H loader mapping (128 threads per K-group), K-tile = 32 fp32 = 16 half2
    const int gtid = tid & 127;
    const int k2 = gtid & 15;            // half2 index within tile
    const int rh = gtid >> 4;            // rows rh + 8i
    // paired store position for half2 index k2 (0..15)
    const int apos = ((k2 >> 3) << 3) | ((k2 & 3) << 1) | ((k2 >> 2) & 1);

    // epilogue mapping: 2 adjacent cells per thread (for half2 packing)
    const int erow = tid >> 2;           // 0..63
    const int ecc  = (tid & 3) * 2;      // 0,2,4,6

    // ---- load resident W (once) as half2 pairs ----
    {
        const int gc  = tid & 31;
        const int g   = gc >> 3;
        const int cl  = gc & 7;
        const int khb = (tid >> 5) * 64;     // each warp covers 64 half2 k-rows
        for (int j = 0; j < 64; j++) {
            const int kh = khb + j;          // 0..511
            const int k  = kh * 2;
            const float lo = Wg[g][(size_t)k * HID + colbase + cl];
            const float hi = Wg[g][(size_t)(k + 1) * HID + colbase + cl];
            const int kc16 = kh >> 3;
            const int win  = kh & 7;
            Wp[kc16][win & 3][gc][win >> 2] = pack_h2(lo, hi);
        }
    }
    __syncthreads();

    for (int t = 0; t < T_STEPS; t++) {
        const float* Xp_t = g_Xp + (size_t)t * BATCH * N4;
        float* Hout = out + (size_t)t * BATCH * HID;

        // ---- prefetch Xp for the epilogue (overlaps GEMM) ----
        float2 xp[4];
        {
            const size_t xb = (size_t)erow * N4 + colbase + ecc;
            #pragma unroll
            for (int g = 0; g < 4; g++)
                xp[g] = *(const float2*)&Xp_t[xb + (size_t)g * HID];
        }

        float c[2][2][4];
        #pragma unroll
        for (int mt = 0; mt < 2; mt++)
            #pragma unroll
            for (int nt = 0; nt < 2; nt++)
                #pragma unroll
                for (int r = 0; r < 4; r++) c[mt][nt][r] = 0.0f;

        const int khbase = kg * 256;     // this half's half2-K origin

        // preload H k-tile 0 (raw u32 half2 from g_Hh)
        #pragma unroll
        for (int i = 0; i < 8; i++) {
            const int row = rh + 8 * i;
            As[kg][0][row][apos] = __ldcg(&g_Hh[row * 512 + khbase + k2]);
        }
        __syncthreads();

        int buf = 0;
        for (int kt2 = 0; kt2 < 16; kt2++) {
            uint32_t hreg[8];
            const bool has_next = (kt2 + 1 < 16);
            if (has_next) {
                const int kh0 = khbase + (kt2 + 1) * 16;
                #pragma unroll
                for (int i = 0; i < 8; i++)
                    hreg[i] = __ldcg(&g_Hh[(rh + 8 * i) * 512 + kh0 + k2]);
            }

            // compute on buf: 2 chunks of K=16
            #pragma unroll
            for (int ch = 0; ch < 2; ch++) {
                const int kc16 = (kg * 16 + kt2) * 2 + ch;
                uint2 a01[2], a23[2];
                #pragma unroll
                for (int mt = 0; mt < 2; mt++) {
                    const int m = 32 * wm + 16 * mt;
                    a01[mt] = *(const uint2*)&As[kg][buf][m + qg][ch * 8 + 2 * qk];
                    a23[mt] = *(const uint2*)&As[kg][buf][m + qg + 8][ch * 8 + 2 * qk];
                }
                uint2 bp[2];
                #pragma unroll
                for (int nt = 0; nt < 2; nt++) {
                    const int n = 16 * wn + 8 * nt;
                    bp[nt] = *(const uint2*)&Wp[kc16][qk][n + qg][0];
                }
                #pragma unroll
                for (int mt = 0; mt < 2; mt++)
                    #pragma unroll
                    for (int nt = 0; nt < 2; nt++)
                        mma_f16(c[mt][nt][0], c[mt][nt][1], c[mt][nt][2], c[mt][nt][3],
                                a01[mt].x, a23[mt].x, a01[mt].y, a23[mt].y,
                                bp[nt].x, bp[nt].y);
            }

            if (has_next) {
                const int nb = buf ^ 1;
                #pragma unroll
                for (int i = 0; i < 8; i++)
                    As[kg][nb][rh + 8 * i][apos] = hreg[i];
                __syncthreads();
                buf = nb;
            }
        }

        // stash per-K-group gate partials
        #pragma unroll
        for (int mt = 0; mt < 2; mt++) {
            #pragma unroll
            for (int nt = 0; nt < 2; nt++) {
                const int row = 32 * wm + 16 * mt + qg;
                const int cn  = 16 * wn + 8 * nt + 2 * qk;
                sg[kg][row][cn]         = c[mt][nt][0];
                sg[kg][row][cn + 1]     = c[mt][nt][1];
                sg[kg][row + 8][cn]     = c[mt][nt][2];
                sg[kg][row + 8][cn + 1] = c[mt][nt][3];
            }
        }
        __syncthreads();

        // ---- fused LSTM cell epilogue: 2 adjacent cells per thread ----
        {
            const int idx = erow * HID + colbase + ecc;
            float2 cprev = *(const float2*)&g_C[idx];
            float hv[2], cv[2];
            #pragma unroll
            for (int s = 0; s < 2; s++) {
                const int cc = ecc + s;
                float gi = sg[0][erow][0  + cc] + sg[1][erow][0  + cc] + (s ? xp[0].y : xp[0].x);
                float gf = sg[0][erow][8  + cc] + sg[1][erow][8  + cc] + (s ? xp[1].y : xp[1].x);
                float go = sg[0][erow][16 + cc] + sg[1][erow][16 + cc] + (s ? xp[2].y : xp[2].x);
                float gg = sg[0][erow][24 + cc] + sg[1][erow][24 + cc] + (s ? xp[3].y : xp[3].x);

                float I = 1.0f / (1.0f + __expf(-gi));
                float F = 1.0f / (1.0f + __expf(-gf));
                float O = 1.0f / (1.0f + __expf(-go));
                float G = tanhf(gg);

                cv[s] = fmaf(F, (s ? cprev.y : cprev.x), I * G);
                hv[s] = O * tanhf(cv[s]);
            }
            *(float2*)&g_C[idx] = make_float2(cv[0], cv[1]);
            __stcg((float2*)&Hout[idx], make_float2(hv[0], hv[1]));
            __stcg(&g_Hh[erow * 512 + ((colbase + ecc) >> 1)], pack_h2(hv[0], hv[1]));
        }

        // ---- grid barrier (R11-proven): release -> arrive -> acquire ----
        __threadfence();
        __syncthreads();
        if (tid == 0) {
            bar_red_release(&g_bar, 1u);
            const unsigned target = (unsigned)NBLK * (unsigned)(t + 1);
            while (bar_ld_acquire(&g_bar) < target) {}
        }
        __syncthreads();
        fence_acq_rel_gpu();
    }
}

// ---------------- tail: H_f and C_f after outputs ---------------------------
__global__ void finalize_kernel(float* __restrict__ out) {
    int i = blockIdx.x * 256 + threadIdx.x;
    if (i < BATCH * HID) {
        size_t base = (size_t)T_STEPS * BATCH * HID;
        out[base + i] = out[(size_t)(T_STEPS - 1) * BATCH * HID + i];  // H_f
        out[base + BATCH * HID + i] = g_C[i];                          // C_f
    }
}

// ---------------- launch -----------------------------------------------------
extern "C" void kernel_launch(void* const* d_in, const int* in_sizes, int n_in,
                              void* d_out, int out_size) {
    const float* X   = (const float*)d_in[0];
    const float* H0  = (const float*)d_in[1];
    const float* C0  = (const float*)d_in[2];
    const float* Wxi = (const float*)d_in[3];
    const float* Wxf = (const float*)d_in[4];
    const float* Wxo = (const float*)d_in[5];
    const float* Wxc = (const float*)d_in[6];
    const float* Whi = (const float*)d_in[7];
    const float* Whf = (const float*)d_in[8];
    const float* Who = (const float*)d_in[9];
    const float* Whc = (const float*)d_in[10];
    const float* bi  = (const float*)d_in[11];
    const float* bf  = (const float*)d_in[12];
    const float* bo  = (const float*)d_in[13];
    const float* bc  = (const float*)d_in[14];
    float* out = (float*)d_out;

    cudaFuncSetAttribute(lstm_persistent,
                         cudaFuncAttributeMaxDynamicSharedMemorySize, SMEM_BYTES);

    init_c_kernel<<<256, 256>>>(C0, H0);
    xproj_tf32_kernel<<<dim3(32, 256), 256>>>(X, Wxi, Wxf, Wxo, Wxc,
                                              bi, bf, bo, bc);
    lstm_persistent<<<NBLK, 256, SMEM_BYTES>>>(Whi, Whf, Who, Whc, out);
    finalize_kernel<<<256, 256>>>(out);
}

// round 14
// speedup vs baseline: 1.5364x; 1.0888x over previous
#include <cuda_runtime.h>
#include <cuda_fp16.h>
#include <math.h>
#include <stdint.h>

#define T_STEPS 512
#define BATCH   64
#define DIM     1024
#define HID     1024
#define N4      4096                 // 4 * HID
#define M_TOT   (T_STEPS * BATCH)    // 32768
#define NBLK    128                  // persistent blocks (<=148 SMs, 1/SM)

// ---------------- scratch (static device globals; no runtime allocation) ----
__device__ float g_Xp[(size_t)M_TOT * N4];   // 512 MB: X @ Wx + b, [T*B, 4H]
__device__ float g_C[BATCH * HID];           // cell state
__device__ uint32_t g_Hh[BATCH * HID / 2];   // H(t) as packed half2 [row][k/2]
__device__ unsigned int g_bar;               // software grid barrier counter

// ---------------- init: cell state, H0 half2 staging, barrier ----------------
__global__ void init_c_kernel(const float* __restrict__ C0,
                              const float* __restrict__ H0) {
    int i = blockIdx.x * 256 + threadIdx.x;
    if (i < BATCH * HID) g_C[i] = C0[i];
    if (i < BATCH * HID / 2) {
        __half2 h = __floats2half2_rn(H0[2 * i], H0[2 * i + 1]);
        g_Hh[i] = *(uint32_t*)&h;
    }
    if (i == 0) g_bar = 0u;
}

// ---------------- helpers ----------------------------------------------------
__device__ __forceinline__ uint32_t pack_h2(float lo, float hi) {
    __half2 h = __floats2half2_rn(lo, hi);
    return *(uint32_t*)&h;
}

__device__ __forceinline__ void mma_f16(float& c0, float& c1, float& c2, float& c3,
                                        uint32_t a0, uint32_t a1, uint32_t a2, uint32_t a3,
                                        uint32_t b0, uint32_t b1) {
    asm volatile(
        "mma.sync.aligned.m16n8k16.row.col.f32.f16.f16.f32 "
        "{%0,%1,%2,%3}, {%4,%5,%6,%7}, {%8,%9}, {%0,%1,%2,%3};\n"
        : "+f"(c0), "+f"(c1), "+f"(c2), "+f"(c3)
        : "r"(a0), "r"(a1), "r"(a2), "r"(a3), "r"(b0), "r"(b1));
}

__device__ __forceinline__ unsigned bar_ld_acquire(const unsigned* p) {
    unsigned v;
    asm volatile("ld.global.acquire.gpu.u32 %0, [%1];" : "=r"(v) : "l"(p) : "memory");
    return v;
}
__device__ __forceinline__ void bar_red_release(unsigned* p, unsigned v) {
    asm volatile("red.release.gpu.global.add.u32 [%0], %1;" :: "l"(p), "r"(v) : "memory");
}
__device__ __forceinline__ void fence_acq_rel_gpu() {
    asm volatile("fence.acq_rel.gpu;" ::: "memory");
}

// ---------------- big GEMM (fp16 tensor cores): g_Xp = X @ Wx + b ------------
// 128x128 output tile per block, BK=16, 256 threads = 8 warps (2x4 warp grid),
// each warp 64x32 via 4x4 m16n8k16 fragments. Smem holds packed half2 with
// k-pair layout: pos(j) = 2*(j&3) + (j>>2), so fragment j-pairs (qk, qk+4)
// sit adjacent -> one LDS.64 per fragment operand.
__global__ __launch_bounds__(256)
void xproj_f16_kernel(const float* __restrict__ X,
                      const float* __restrict__ W0, const float* __restrict__ W1,
                      const float* __restrict__ W2, const float* __restrict__ W3,
                      const float* __restrict__ b0, const float* __restrict__ b1,
                      const float* __restrict__ b2, const float* __restrict__ b3) {
    const int bn = blockIdx.x * 128;
    const int bm = blockIdx.y * 128;
    const int gate = bn >> 10;
    const float* W  = (gate == 0) ? W0 : (gate == 1) ? W1 : (gate == 2) ? W2 : W3;
    const float* bb = (gate == 0) ? b0 : (gate == 1) ? b1 : (gate == 2) ? b2 : b3;
    const int col0 = bn & (HID - 1);

    __shared__ uint32_t As[2][128][10];   // [m][8 k-pair slots, pad 10]
    __shared__ uint32_t Bs[2][128][10];   // [n][8 k-pair slots, pad 10]

    const int tid  = threadIdx.x;
    const int lane = tid & 31;
    const int warp = tid >> 5;
    const int wm   = warp >> 2;          // m offset wm*64
    const int wn   = warp & 3;           // n offset wn*32
    const int qg   = lane >> 2;
    const int qk   = lane & 3;

    // A loader: row ar, 8 consecutive k (= 4 half2, j = jb..jb+3)
    const int ar    = tid >> 1;          // 0..127
    const int ac    = (tid & 1) * 8;     // k base 0 or 8
    const int psela = tid & 1;           // pos parity (jb>>2)
    // B loader: col bc, 4 half2 (j = jb2..jb2+3)
    const int bc    = tid & 127;
    const int pselb = tid >> 7;          // 0/1
    const int jb2   = pselb * 4;

    float c[4][4][4];
    #pragma unroll
    for (int mt = 0; mt < 4; mt++)
        #pragma unroll
        for (int nt = 0; nt < 4; nt++)
            #pragma unroll
            for (int r = 0; r < 4; r++) c[mt][nt][r] = 0.0f;

    // ---- preload k-tile 0 ----
    {
        float4 av0 = *(const float4*)&X[(size_t)(bm + ar) * DIM + ac];
        float4 av1 = *(const float4*)&X[(size_t)(bm + ar) * DIM + ac + 4];
        As[0][ar][0 + psela] = pack_h2(av0.x, av0.y);
        As[0][ar][2 + psela] = pack_h2(av0.z, av0.w);
        As[0][ar][4 + psela] = pack_h2(av1.x, av1.y);
        As[0][ar][6 + psela] = pack_h2(av1.z, av1.w);
        #pragma unroll
        for (int i = 0; i < 4; i++) {
            const int j = jb2 + i;
            float lo = W[(size_t)(2 * j)     * HID + col0 + bc];
            float hi = W[(size_t)(2 * j + 1) * HID + col0 + bc];
            Bs[0][bc][2 * i + pselb] = pack_h2(lo, hi);
        }
    }
    __syncthreads();

    int buf = 0;
    for (int kt = 0; kt < DIM / 16; kt++) {
        float4 av0, av1;
        float blo[4], bhi[4];
        const int k0n = (kt + 1) * 16;
        const bool has_next = (kt + 1 < DIM / 16);
        if (has_next) {
            av0 = *(const float4*)&X[(size_t)(bm + ar) * DIM + k0n + ac];
            av1 = *(const float4*)&X[(size_t)(bm + ar) * DIM + k0n + ac + 4];
            #pragma unroll
            for (int i = 0; i < 4; i++) {
                const int j = jb2 + i;
                blo[i] = W[(size_t)(k0n + 2 * j)     * HID + col0 + bc];
                bhi[i] = W[(size_t)(k0n + 2 * j + 1) * HID + col0 + bc];
            }
        }

        // ---- compute on current buffer: one K=16 chunk ----
        {
            uint2 a0p[4], a1p[4];
            #pragma unroll
            for (int mt = 0; mt < 4; mt++) {
                const int m = wm * 64 + mt * 16;
                a0p[mt] = *(const uint2*)&As[buf][m + qg][2 * qk];
                a1p[mt] = *(const uint2*)&As[buf][m + qg + 8][2 * qk];
            }
            uint2 bp[4];
            #pragma unroll
            for (int nt = 0; nt < 4; nt++) {
                const int n = wn * 32 + nt * 8;
                bp[nt] = *(const uint2*)&Bs[buf][n + qg][2 * qk];
            }
            #pragma unroll
            for (int mt = 0; mt < 4; mt++)
                #pragma unroll
                for (int nt = 0; nt < 4; nt++)
                    mma_f16(c[mt][nt][0], c[mt][nt][1], c[mt][nt][2], c[mt][nt][3],
                            a0p[mt].x, a1p[mt].x, a0p[mt].y, a1p[mt].y,
                            bp[nt].x, bp[nt].y);
        }

        if (has_next) {
            const int nb = buf ^ 1;
            As[nb][ar][0 + psela] = pack_h2(av0.x, av0.y);
            As[nb][ar][2 + psela] = pack_h2(av0.z, av0.w);
            As[nb][ar][4 + psela] = pack_h2(av1.x, av1.y);
            As[nb][ar][6 + psela] = pack_h2(av1.z, av1.w);
            #pragma unroll
            for (int i = 0; i < 4; i++)
                Bs[nb][bc][2 * i + pselb] = pack_h2(blo[i], bhi[i]);
            __syncthreads();
            buf = nb;
        }
    }

    // ---- epilogue: add bias, store to g_Xp ----
    #pragma unroll
    for (int mt = 0; mt < 4; mt++) {
        #pragma unroll
        for (int nt = 0; nt < 4; nt++) {
            const int colg = wn * 32 + nt * 8 + 2 * qk;
            const float bx0 = bb[col0 + colg];
            const float bx1 = bb[col0 + colg + 1];
            const size_t row0 = (size_t)(bm + wm * 64 + mt * 16 + qg);
            float2 v0 = make_float2(c[mt][nt][0] + bx0, c[mt][nt][1] + bx1);
            float2 v1 = make_float2(c[mt][nt][2] + bx0, c[mt][nt][3] + bx1);
            *(float2*)&g_Xp[row0 * N4 + bn + colg]       = v0;
            *(float2*)&g_Xp[(row0 + 8) * N4 + bn + colg] = v1;
        }
    }
}

// ---------------- persistent recurrence kernel (fp16 m16n8k16) ---------------
// R13 exactly: K-tile 32 per K-group, counter barrier, half2 H handoff via
// g_Hh, Xp epilogue prefetch.
#define WP_WORDS (64 * 4 * 35 * 2)
#define AS_WORDS (2 * 2 * 64 * 18)
#define SG_WORDS (2 * 64 * 33)
#define SMEM_BYTES ((WP_WORDS + AS_WORDS + SG_WORDS) * 4)

__global__ __launch_bounds__(256)
void lstm_persistent(const float* __restrict__ W0, const float* __restrict__ W1,
                     const float* __restrict__ W2, const float* __restrict__ W3,
                     float* __restrict__ out) {
    extern __shared__ unsigned char smem_raw[];
    uint32_t (*Wp)[4][35][2]  = (uint32_t (*)[4][35][2])smem_raw;
    uint32_t (*As)[2][64][18] = (uint32_t (*)[2][64][18])(smem_raw + WP_WORDS * 4);
    float    (*sg)[64][33]    = (float (*)[64][33])(smem_raw + (WP_WORDS + AS_WORDS) * 4);

    const int tid  = threadIdx.x;
    const int lane = tid & 31;
    const int warp = tid >> 5;           // 0..7
    const int colbase = blockIdx.x * 8;

    const float* Wg[4] = {W0, W1, W2, W3};

    const int kg = warp >> 2;            // K-group 0/1
    const int wq = warp & 3;
    const int wm = wq >> 1;              // rows 32*wm
    const int wn = wq & 1;               // gate-cols 16*wn
    const int qg = lane >> 2;
    const int qk = lane & 3;

    const int gtid = tid & 127;
    const int k2 = gtid & 15;            // half2 index within tile
    const int rh = gtid >> 4;            // rows rh + 8i
    const int apos = ((k2 >> 3) << 3) | ((k2 & 3) << 1) | ((k2 >> 2) & 1);

    const int erow = tid >> 2;           // 0..63
    const int ecc  = (tid & 3) * 2;      // 0,2,4,6

    // ---- load resident W (once) as half2 pairs ----
    {
        const int gc  = tid & 31;
        const int g   = gc >> 3;
        const int cl  = gc & 7;
        const int khb = (tid >> 5) * 64;
        for (int j = 0; j < 64; j++) {
            const int kh = khb + j;
            const int k  = kh * 2;
            const float lo = Wg[g][(size_t)k * HID + colbase + cl];
            const float hi = Wg[g][(size_t)(k + 1) * HID + colbase + cl];
            const int kc16 = kh >> 3;
            const int win  = kh & 7;
            Wp[kc16][win & 3][gc][win >> 2] = pack_h2(lo, hi);
        }
    }
    __syncthreads();

    for (int t = 0; t < T_STEPS; t++) {
        const float* Xp_t = g_Xp + (size_t)t * BATCH * N4;
        float* Hout = out + (size_t)t * BATCH * HID;

        // ---- prefetch Xp for the epilogue (overlaps GEMM) ----
        float2 xp[4];
        {
            const size_t xb = (size_t)erow * N4 + colbase + ecc;
            #pragma unroll
            for (int g = 0; g < 4; g++)
                xp[g] = *(const float2*)&Xp_t[xb + (size_t)g * HID];
        }

        float c[2][2][4];
        #pragma unroll
        for (int mt = 0; mt < 2; mt++)
            #pragma unroll
            for (int nt = 0; nt < 2; nt++)
                #pragma unroll
                for (int r = 0; r < 4; r++) c[mt][nt][r] = 0.0f;

        const int khbase = kg * 256;

        #pragma unroll
        for (int i = 0; i < 8; i++) {
            const int row = rh + 8 * i;
            As[kg][0][row][apos] = __ldcg(&g_Hh[row * 512 + khbase + k2]);
        }
        __syncthreads();

        int buf = 0;
        for (int kt2 = 0; kt2 < 16; kt2++) {
            uint32_t hreg[8];
            const bool has_next = (kt2 + 1 < 16);
            if (has_next) {
                const int kh0 = khbase + (kt2 + 1) * 16;
                #pragma unroll
                for (int i = 0; i < 8; i++)
                    hreg[i] = __ldcg(&g_Hh[(rh + 8 * i) * 512 + kh0 + k2]);
            }

            #pragma unroll
            for (int ch = 0; ch < 2; ch++) {
                const int kc16 = (kg * 16 + kt2) * 2 + ch;
                uint2 a01[2], a23[2];
                #pragma unroll
                for (int mt = 0; mt < 2; mt++) {
                    const int m = 32 * wm + 16 * mt;
                    a01[mt] = *(const uint2*)&As[kg][buf][m + qg][ch * 8 + 2 * qk];
                    a23[mt] = *(const uint2*)&As[kg][buf][m + qg + 8][ch * 8 + 2 * qk];
                }
                uint2 bp[2];
                #pragma unroll
                for (int nt = 0; nt < 2; nt++) {
                    const int n = 16 * wn + 8 * nt;
                    bp[nt] = *(const uint2*)&Wp[kc16][qk][n + qg][0];
                }
                #pragma unroll
                for (int mt = 0; mt < 2; mt++)
                    #pragma unroll
                    for (int nt = 0; nt < 2; nt++)
                        mma_f16(c[mt][nt][0], c[mt][nt][1], c[mt][nt][2], c[mt][nt][3],
                                a01[mt].x, a23[mt].x, a01[mt].y, a23[mt].y,
                                bp[nt].x, bp[nt].y);
            }

            if (has_next) {
                const int nb = buf ^ 1;
                #pragma unroll
                for (int i = 0; i < 8; i++)
                    As[kg][nb][rh + 8 * i][apos] = hreg[i];
                __syncthreads();
                buf = nb;
            }
        }

        // stash per-K-group gate partials
        #pragma unroll
        for (int mt = 0; mt < 2; mt++) {
            #pragma unroll
            for (int nt = 0; nt < 2; nt++) {
                const int row = 32 * wm + 16 * mt + qg;
                const int cn  = 16 * wn + 8 * nt + 2 * qk;
                sg[kg][row][cn]         = c[mt][nt][0];
                sg[kg][row][cn + 1]     = c[mt][nt][1];
                sg[kg][row + 8][cn]     = c[mt][nt][2];
                sg[kg][row + 8][cn + 1] = c[mt][nt][3];
            }
        }
        __syncthreads();

        // ---- fused LSTM cell epilogue: 2 adjacent cells per thread ----
        {
            const int idx = erow * HID + colbase + ecc;
            float2 cprev = *(const float2*)&g_C[idx];
            float hv[2], cv[2];
            #pragma unroll
            for (int s = 0; s < 2; s++) {
                const int cc = ecc + s;
                float gi = sg[0][erow][0  + cc] + sg[1][erow][0  + cc] + (s ? xp[0].y : xp[0].x);
                float gf = sg[0][erow][8  + cc] + sg[1][erow][8  + cc] + (s ? xp[1].y : xp[1].x);
                float go = sg[0][erow][16 + cc] + sg[1][erow][16 + cc] + (s ? xp[2].y : xp[2].x);
                float gg = sg[0][erow][24 + cc] + sg[1][erow][24 + cc] + (s ? xp[3].y : xp[3].x);

                float I = 1.0f / (1.0f + __expf(-gi));
                float F = 1.0f / (1.0f + __expf(-gf));
                float O = 1.0f / (1.0f + __expf(-go));
                float G = tanhf(gg);

                cv[s] = fmaf(F, (s ? cprev.y : cprev.x), I * G);
                hv[s] = O * tanhf(cv[s]);
            }
            *(float2*)&g_C[idx] = make_float2(cv[0], cv[1]);
            __stcg((float2*)&Hout[idx], make_float2(hv[0], hv[1]));
            __stcg(&g_Hh[erow * 512 + ((colbase + ecc) >> 1)], pack_h2(hv[0], hv[1]));
        }

        // ---- grid barrier: release -> arrive -> acquire ----
        __threadfence();
        __syncthreads();
        if (tid == 0) {
            bar_red_release(&g_bar, 1u);
            const unsigned target = (unsigned)NBLK * (unsigned)(t + 1);
            while (bar_ld_acquire(&g_bar) < target) {}
        }
        __syncthreads();
        fence_acq_rel_gpu();
    }
}

// ---------------- tail: H_f and C_f after outputs ---------------------------
__global__ void finalize_kernel(float* __restrict__ out) {
    int i = blockIdx.x * 256 + threadIdx.x;
    if (i < BATCH * HID) {
        size_t base = (size_t)T_STEPS * BATCH * HID;
        out[base + i] = out[(size_t)(T_STEPS - 1) * BATCH * HID + i];  // H_f
        out[base + BATCH * HID + i] = g_C[i];                          // C_f
    }
}

// ---------------- launch -----------------------------------------------------
extern "C" void kernel_launch(void* const* d_in, const int* in_sizes, int n_in,
                              void* d_out, int out_size) {
    const float* X   = (const float*)d_in[0];
    const float* H0  = (const float*)d_in[1];
    const float* C0  = (const float*)d_in[2];
    const float* Wxi = (const float*)d_in[3];
    const float* Wxf = (const float*)d_in[4];
    const float* Wxo = (const float*)d_in[5];
    const float* Wxc = (const float*)d_in[6];
    const float* Whi = (const float*)d_in[7];
    const float* Whf = (const float*)d_in[8];
    const float* Who = (const float*)d_in[9];
    const float* Whc = (const float*)d_in[10];
    const float* bi  = (const float*)d_in[11];
    const float* bf  = (const float*)d_in[12];
    const float* bo  = (const float*)d_in[13];
    const float* bc  = (const float*)d_in[14];
    float* out = (float*)d_out;

    cudaFuncSetAttribute(lstm_persistent,
                         cudaFuncAttributeMaxDynamicSharedMemorySize, SMEM_BYTES);

    init_c_kernel<<<256, 256>>>(C0, H0);
    xproj_f16_kernel<<<dim3(32, 256), 256>>>(X, Wxi, Wxf, Wxo, Wxc,
                                             bi, bf, bo, bc);
    lstm_persistent<<<NBLK, 256, SMEM_BYTES>>>(Whi, Whf, Who, Whc, out);
    finalize_kernel<<<256, 256>>>(out);
}

// round 15
// speedup vs baseline: 1.6045x; 1.0443x over previous
#include <cuda_runtime.h>
#include <cuda_fp16.h>
#include <math.h>
#include <stdint.h>

#define T_STEPS 512
#define BATCH   64
#define DIM     1024
#define HID     1024
#define N4      4096                 // 4 * HID
#define M_TOT   (T_STEPS * BATCH)    // 32768
#define NBLK    128                  // persistent blocks (<=148 SMs, 1/SM)

// ---------------- scratch (static device globals; no runtime allocation) ----
__device__ float g_Xp[(size_t)M_TOT * N4];   // 512 MB: X @ Wx + b, [T*B, 4H]
__device__ float g_C[BATCH * HID];           // cell state
__device__ uint32_t g_Hh[BATCH * HID / 2];   // H(t) as packed half2 [row][k/2]
__device__ unsigned int g_bar;               // software grid barrier counter

// ---------------- init: cell state, H0 half2 staging, barrier ----------------
__global__ void init_c_kernel(const float* __restrict__ C0,
                              const float* __restrict__ H0) {
    int i = blockIdx.x * 256 + threadIdx.x;
    if (i < BATCH * HID) g_C[i] = C0[i];
    if (i < BATCH * HID / 2) {
        __half2 h = __floats2half2_rn(H0[2 * i], H0[2 * i + 1]);
        g_Hh[i] = *(uint32_t*)&h;
    }
    if (i == 0) g_bar = 0u;
}

// ---------------- helpers ----------------------------------------------------
__device__ __forceinline__ uint32_t pack_h2(float lo, float hi) {
    __half2 h = __floats2half2_rn(lo, hi);
    return *(uint32_t*)&h;
}

__device__ __forceinline__ void mma_f16(float& c0, float& c1, float& c2, float& c3,
                                        uint32_t a0, uint32_t a1, uint32_t a2, uint32_t a3,
                                        uint32_t b0, uint32_t b1) {
    asm volatile(
        "mma.sync.aligned.m16n8k16.row.col.f32.f16.f16.f32 "
        "{%0,%1,%2,%3}, {%4,%5,%6,%7}, {%8,%9}, {%0,%1,%2,%3};\n"
        : "+f"(c0), "+f"(c1), "+f"(c2), "+f"(c3)
        : "r"(a0), "r"(a1), "r"(a2), "r"(a3), "r"(b0), "r"(b1));
}

__device__ __forceinline__ unsigned bar_ld_acquire(const unsigned* p) {
    unsigned v;
    asm volatile("ld.global.acquire.gpu.u32 %0, [%1];" : "=r"(v) : "l"(p) : "memory");
    return v;
}
__device__ __forceinline__ void bar_red_release(unsigned* p, unsigned v) {
    asm volatile("red.release.gpu.global.add.u32 [%0], %1;" :: "l"(p), "r"(v) : "memory");
}

// ---------------- big GEMM (fp16 tensor cores): g_Xp = X @ Wx + b ------------
// 128x128 output tile per block, BK=16, 256 threads = 8 warps (2x4 warp grid),
// each warp 64x32 via 4x4 m16n8k16 fragments. Smem holds packed half2 with
// k-pair layout: pos(j) = 2*(j&3) + (j>>2), so fragment j-pairs (qk, qk+4)
// sit adjacent -> one LDS.64 per fragment operand.
__global__ __launch_bounds__(256)
void xproj_f16_kernel(const float* __restrict__ X,
                      const float* __restrict__ W0, const float* __restrict__ W1,
                      const float* __restrict__ W2, const float* __restrict__ W3,
                      const float* __restrict__ b0, const float* __restrict__ b1,
                      const float* __restrict__ b2, const float* __restrict__ b3) {
    const int bn = blockIdx.x * 128;
    const int bm = blockIdx.y * 128;
    const int gate = bn >> 10;
    const float* W  = (gate == 0) ? W0 : (gate == 1) ? W1 : (gate == 2) ? W2 : W3;
    const float* bb = (gate == 0) ? b0 : (gate == 1) ? b1 : (gate == 2) ? b2 : b3;
    const int col0 = bn & (HID - 1);

    __shared__ uint32_t As[2][128][10];   // [m][8 k-pair slots, pad 10]
    __shared__ uint32_t Bs[2][128][10];   // [n][8 k-pair slots, pad 10]

    const int tid  = threadIdx.x;
    const int lane = tid & 31;
    const int warp = tid >> 5;
    const int wm   = warp >> 2;          // m offset wm*64
    const int wn   = warp & 3;           // n offset wn*32
    const int qg   = lane >> 2;
    const int qk   = lane & 3;

    const int ar    = tid >> 1;          // 0..127
    const int ac    = (tid & 1) * 8;     // k base 0 or 8
    const int psela = tid & 1;           // pos parity
    const int bc    = tid & 127;
    const int pselb = tid >> 7;          // 0/1
    const int jb2   = pselb * 4;

    float c[4][4][4];
    #pragma unroll
    for (int mt = 0; mt < 4; mt++)
        #pragma unroll
        for (int nt = 0; nt < 4; nt++)
            #pragma unroll
            for (int r = 0; r < 4; r++) c[mt][nt][r] = 0.0f;

    // ---- preload k-tile 0 ----
    {
        float4 av0 = *(const float4*)&X[(size_t)(bm + ar) * DIM + ac];
        float4 av1 = *(const float4*)&X[(size_t)(bm + ar) * DIM + ac + 4];
        As[0][ar][0 + psela] = pack_h2(av0.x, av0.y);
        As[0][ar][2 + psela] = pack_h2(av0.z, av0.w);
        As[0][ar][4 + psela] = pack_h2(av1.x, av1.y);
        As[0][ar][6 + psela] = pack_h2(av1.z, av1.w);
        #pragma unroll
        for (int i = 0; i < 4; i++) {
            const int j = jb2 + i;
            float lo = W[(size_t)(2 * j)     * HID + col0 + bc];
            float hi = W[(size_t)(2 * j + 1) * HID + col0 + bc];
            Bs[0][bc][2 * i + pselb] = pack_h2(lo, hi);
        }
    }
    __syncthreads();

    int buf = 0;
    for (int kt = 0; kt < DIM / 16; kt++) {
        float4 av0, av1;
        float blo[4], bhi[4];
        const int k0n = (kt + 1) * 16;
        const bool has_next = (kt + 1 < DIM / 16);
        if (has_next) {
            av0 = *(const float4*)&X[(size_t)(bm + ar) * DIM + k0n + ac];
            av1 = *(const float4*)&X[(size_t)(bm + ar) * DIM + k0n + ac + 4];
            #pragma unroll
            for (int i = 0; i < 4; i++) {
                const int j = jb2 + i;
                blo[i] = W[(size_t)(k0n + 2 * j)     * HID + col0 + bc];
                bhi[i] = W[(size_t)(k0n + 2 * j + 1) * HID + col0 + bc];
            }
        }

        {
            uint2 a0p[4], a1p[4];
            #pragma unroll
            for (int mt = 0; mt < 4; mt++) {
                const int m = wm * 64 + mt * 16;
                a0p[mt] = *(const uint2*)&As[buf][m + qg][2 * qk];
                a1p[mt] = *(const uint2*)&As[buf][m + qg + 8][2 * qk];
            }
            uint2 bp[4];
            #pragma unroll
            for (int nt = 0; nt < 4; nt++) {
                const int n = wn * 32 + nt * 8;
                bp[nt] = *(const uint2*)&Bs[buf][n + qg][2 * qk];
            }
            #pragma unroll
            for (int mt = 0; mt < 4; mt++)
                #pragma unroll
                for (int nt = 0; nt < 4; nt++)
                    mma_f16(c[mt][nt][0], c[mt][nt][1], c[mt][nt][2], c[mt][nt][3],
                            a0p[mt].x, a1p[mt].x, a0p[mt].y, a1p[mt].y,
                            bp[nt].x, bp[nt].y);
        }

        if (has_next) {
            const int nb = buf ^ 1;
            As[nb][ar][0 + psela] = pack_h2(av0.x, av0.y);
            As[nb][ar][2 + psela] = pack_h2(av0.z, av0.w);
            As[nb][ar][4 + psela] = pack_h2(av1.x, av1.y);
            As[nb][ar][6 + psela] = pack_h2(av1.z, av1.w);
            #pragma unroll
            for (int i = 0; i < 4; i++)
                Bs[nb][bc][2 * i + pselb] = pack_h2(blo[i], bhi[i]);
            __syncthreads();
            buf = nb;
        }
    }

    // ---- epilogue: add bias, store to g_Xp ----
    #pragma unroll
    for (int mt = 0; mt < 4; mt++) {
        #pragma unroll
        for (int nt = 0; nt < 4; nt++) {
            const int colg = wn * 32 + nt * 8 + 2 * qk;
            const float bx0 = bb[col0 + colg];
            const float bx1 = bb[col0 + colg + 1];
            const size_t row0 = (size_t)(bm + wm * 64 + mt * 16 + qg);
            float2 v0 = make_float2(c[mt][nt][0] + bx0, c[mt][nt][1] + bx1);
            float2 v1 = make_float2(c[mt][nt][2] + bx0, c[mt][nt][3] + bx1);
            *(float2*)&g_Xp[row0 * N4 + bn + colg]       = v0;
            *(float2*)&g_Xp[(row0 + 8) * N4 + bn + colg] = v1;
        }
    }
}

// ---------------- persistent recurrence kernel (fp16 m16n8k16) ---------------
// R13/R14 structure; barrier slimmed to the canonical CG grid-sync pattern
// (bar.sync -> tid0 red.release + acquire-poll -> bar.sync; causality chains
// through bar.sync, no per-thread membar). Next-step Xp prefetch issued
// BEFORE the barrier so its DRAM latency overlaps the barrier wait.
#define WP_WORDS (64 * 4 * 35 * 2)
#define AS_WORDS (2 * 2 * 64 * 18)
#define SG_WORDS (2 * 64 * 33)
#define SMEM_BYTES ((WP_WORDS + AS_WORDS + SG_WORDS) * 4)

__global__ __launch_bounds__(256)
void lstm_persistent(const float* __restrict__ W0, const float* __restrict__ W1,
                     const float* __restrict__ W2, const float* __restrict__ W3,
                     float* __restrict__ out) {
    extern __shared__ unsigned char smem_raw[];
    uint32_t (*Wp)[4][35][2]  = (uint32_t (*)[4][35][2])smem_raw;
    uint32_t (*As)[2][64][18] = (uint32_t (*)[2][64][18])(smem_raw + WP_WORDS * 4);
    float    (*sg)[64][33]    = (float (*)[64][33])(smem_raw + (WP_WORDS + AS_WORDS) * 4);

    const int tid  = threadIdx.x;
    const int lane = tid & 31;
    const int warp = tid >> 5;           // 0..7
    const int colbase = blockIdx.x * 8;

    const float* Wg[4] = {W0, W1, W2, W3};

    const int kg = warp >> 2;            // K-group 0/1
    const int wq = warp & 3;
    const int wm = wq >> 1;              // rows 32*wm
    const int wn = wq & 1;               // gate-cols 16*wn
    const int qg = lane >> 2;
    const int qk = lane & 3;

    const int gtid = tid & 127;
    const int k2 = gtid & 15;            // half2 index within tile
    const int rh = gtid >> 4;            // rows rh + 8i
    const int apos = ((k2 >> 3) << 3) | ((k2 & 3) << 1) | ((k2 >> 2) & 1);

    const int erow = tid >> 2;           // 0..63
    const int ecc  = (tid & 3) * 2;      // 0,2,4,6
    const size_t xpb = (size_t)erow * N4 + colbase + ecc;

    // ---- load resident W (once) as half2 pairs ----
    {
        const int gc  = tid & 31;
        const int g   = gc >> 3;
        const int cl  = gc & 7;
        const int khb = (tid >> 5) * 64;
        for (int j = 0; j < 64; j++) {
            const int kh = khb + j;
            const int k  = kh * 2;
            const float lo = Wg[g][(size_t)k * HID + colbase + cl];
            const float hi = Wg[g][(size_t)(k + 1) * HID + colbase + cl];
            const int kc16 = kh >> 3;
            const int win  = kh & 7;
            Wp[kc16][win & 3][gc][win >> 2] = pack_h2(lo, hi);
        }
    }
    __syncthreads();

    // ---- prefetch Xp for step 0 ----
    float2 xp[4];
    #pragma unroll
    for (int g = 0; g < 4; g++)
        xp[g] = *(const float2*)&g_Xp[xpb + (size_t)g * HID];

    for (int t = 0; t < T_STEPS; t++) {
        float* Hout = out + (size_t)t * BATCH * HID;

        float c[2][2][4];
        #pragma unroll
        for (int mt = 0; mt < 2; mt++)
            #pragma unroll
            for (int nt = 0; nt < 2; nt++)
                #pragma unroll
                for (int r = 0; r < 4; r++) c[mt][nt][r] = 0.0f;

        const int khbase = kg * 256;

        // preload H k-tile 0 (raw u32 half2 from g_Hh)
        #pragma unroll
        for (int i = 0; i < 8; i++) {
            const int row = rh + 8 * i;
            As[kg][0][row][apos] = __ldcg(&g_Hh[row * 512 + khbase + k2]);
        }
        __syncthreads();

        int buf = 0;
        for (int kt2 = 0; kt2 < 16; kt2++) {
            uint32_t hreg[8];
            const bool has_next = (kt2 + 1 < 16);
            if (has_next) {
                const int kh0 = khbase + (kt2 + 1) * 16;
                #pragma unroll
                for (int i = 0; i < 8; i++)
                    hreg[i] = __ldcg(&g_Hh[(rh + 8 * i) * 512 + kh0 + k2]);
            }

            #pragma unroll
            for (int ch = 0; ch < 2; ch++) {
                const int kc16 = (kg * 16 + kt2) * 2 + ch;
                uint2 a01[2], a23[2];
                #pragma unroll
                for (int mt = 0; mt < 2; mt++) {
                    const int m = 32 * wm + 16 * mt;
                    a01[mt] = *(const uint2*)&As[kg][buf][m + qg][ch * 8 + 2 * qk];
                    a23[mt] = *(const uint2*)&As[kg][buf][m + qg + 8][ch * 8 + 2 * qk];
                }
                uint2 bp[2];
                #pragma unroll
                for (int nt = 0; nt < 2; nt++) {
                    const int n = 16 * wn + 8 * nt;
                    bp[nt] = *(const uint2*)&Wp[kc16][qk][n + qg][0];
                }
                #pragma unroll
                for (int mt = 0; mt < 2; mt++)
                    #pragma unroll
                    for (int nt = 0; nt < 2; nt++)
                        mma_f16(c[mt][nt][0], c[mt][nt][1], c[mt][nt][2], c[mt][nt][3],
                                a01[mt].x, a23[mt].x, a01[mt].y, a23[mt].y,
                                bp[nt].x, bp[nt].y);
            }

            if (has_next) {
                const int nb = buf ^ 1;
                #pragma unroll
                for (int i = 0; i < 8; i++)
                    As[kg][nb][rh + 8 * i][apos] = hreg[i];
                __syncthreads();
                buf = nb;
            }
        }

        // stash per-K-group gate partials
        #pragma unroll
        for (int mt = 0; mt < 2; mt++) {
            #pragma unroll
            for (int nt = 0; nt < 2; nt++) {
                const int row = 32 * wm + 16 * mt + qg;
                const int cn  = 16 * wn + 8 * nt + 2 * qk;
                sg[kg][row][cn]         = c[mt][nt][0];
                sg[kg][row][cn + 1]     = c[mt][nt][1];
                sg[kg][row + 8][cn]     = c[mt][nt][2];
                sg[kg][row + 8][cn + 1] = c[mt][nt][3];
            }
        }
        __syncthreads();

        // ---- fused LSTM cell epilogue: 2 adjacent cells per thread ----
        {
            const int idx = erow * HID + colbase + ecc;
            float2 cprev = *(const float2*)&g_C[idx];
            float hv[2], cv[2];
            #pragma unroll
            for (int s = 0; s < 2; s++) {
                const int cc = ecc + s;
                float gi = sg[0][erow][0  + cc] + sg[1][erow][0  + cc] + (s ? xp[0].y : xp[0].x);
                float gf = sg[0][erow][8  + cc] + sg[1][erow][8  + cc] + (s ? xp[1].y : xp[1].x);
                float go = sg[0][erow][16 + cc] + sg[1][erow][16 + cc] + (s ? xp[2].y : xp[2].x);
                float gg = sg[0][erow][24 + cc] + sg[1][erow][24 + cc] + (s ? xp[3].y : xp[3].x);

                float I = 1.0f / (1.0f + __expf(-gi));
                float F = 1.0f / (1.0f + __expf(-gf));
                float O = 1.0f / (1.0f + __expf(-go));
                float G = tanhf(gg);

                cv[s] = fmaf(F, (s ? cprev.y : cprev.x), I * G);
                hv[s] = O * tanhf(cv[s]);
            }
            *(float2*)&g_C[idx] = make_float2(cv[0], cv[1]);
            __stcg((float2*)&Hout[idx], make_float2(hv[0], hv[1]));
            __stcg(&g_Hh[erow * 512 + ((colbase + ecc) >> 1)], pack_h2(hv[0], hv[1]));
        }

        // ---- prefetch next step's Xp (read-only; overlaps barrier wait) ----
        if (t + 1 < T_STEPS) {
            const float* Xp_n = g_Xp + (size_t)(t + 1) * BATCH * N4;
            #pragma unroll
            for (int g = 0; g < 4; g++)
                xp[g] = *(const float2*)&Xp_n[xpb + (size_t)g * HID];
        }

        // ---- grid barrier (canonical CG pattern; causality via bar.sync) ----
        __syncthreads();                     // all stores done, block-wide
        if (tid == 0) {
            bar_red_release(&g_bar, 1u);     // release: publishes CTA's stores
            const unsigned target = (unsigned)NBLK * (unsigned)(t + 1);
            while (bar_ld_acquire(&g_bar) < target) {}   // acquire
        }
        __syncthreads();                     // broadcast acquire to all threads
    }
}

// ---------------- tail: H_f and C_f after outputs ---------------------------
__global__ void finalize_kernel(float* __restrict__ out) {
    int i = blockIdx.x * 256 + threadIdx.x;
    if (i < BATCH * HID) {
        size_t base = (size_t)T_STEPS * BATCH * HID;
        out[base + i] = out[(size_t)(T_STEPS - 1) * BATCH * HID + i];  // H_f
        out[base + BATCH * HID + i] = g_C[i];                          // C_f
    }
}

// ---------------- launch -----------------------------------------------------
extern "C" void kernel_launch(void* const* d_in, const int* in_sizes, int n_in,
                              void* d_out, int out_size) {
    const float* X   = (const float*)d_in[0];
    const float* H0  = (const float*)d_in[1];
    const float* C0  = (const float*)d_in[2];
    const float* Wxi = (const float*)d_in[3];
    const float* Wxf = (const float*)d_in[4];
    const float* Wxo = (const float*)d_in[5];
    const float* Wxc = (const float*)d_in[6];
    const float* Whi = (const float*)d_in[7];
    const float* Whf = (const float*)d_in[8];
    const float* Who = (const float*)d_in[9];
    const float* Whc = (const float*)d_in[10];
    const float* bi  = (const float*)d_in[11];
    const float* bf  = (const float*)d_in[12];
    const float* bo  = (const float*)d_in[13];
    const float* bc  = (const float*)d_in[14];
    float* out = (float*)d_out;

    cudaFuncSetAttribute(lstm_persistent,
                         cudaFuncAttributeMaxDynamicSharedMemorySize, SMEM_BYTES);

    init_c_kernel<<<256, 256>>>(C0, H0);
    xproj_f16_kernel<<<dim3(32, 256), 256>>>(X, Wxi, Wxf, Wxo, Wxc,
                                             bi, bf, bo, bc);
    lstm_persistent<<<NBLK, 256, SMEM_BYTES>>>(Whi, Whf, Who, Whc, out);
    finalize_kernel<<<256, 256>>>(out);
}

// round 16
// speedup vs baseline: 1.9297x; 1.2027x over previous
#include <cuda_runtime.h>
#include <cuda_fp16.h>
#include <math.h>
#include <stdint.h>

#define T_STEPS 512
#define BATCH   64
#define DIM     1024
#define HID     1024
#define N4      4096                 // 4 * HID
#define M_TOT   (T_STEPS * BATCH)    // 32768
#define NBLK    128                  // persistent blocks (<=148 SMs, 1/SM)

// ---------------- scratch (static device globals; no runtime allocation) ----
__device__ float g_Xp[(size_t)M_TOT * N4];   // 512 MB: X @ Wx + b, [T*B, 4H]
__device__ float g_C[BATCH * HID];           // cell state
__device__ uint32_t g_Hh[BATCH * HID / 2];   // H(t) as packed half2 [row][k/2]
__device__ unsigned int g_bar;               // software grid barrier counter

// ---------------- init: cell state, H0 half2 staging, barrier ----------------
__global__ void init_c_kernel(const float* __restrict__ C0,
                              const float* __restrict__ H0) {
    int i = blockIdx.x * 256 + threadIdx.x;
    if (i < BATCH * HID) g_C[i] = C0[i];
    if (i < BATCH * HID / 2) {
        __half2 h = __floats2half2_rn(H0[2 * i], H0[2 * i + 1]);
        g_Hh[i] = *(uint32_t*)&h;
    }
    if (i == 0) g_bar = 0u;
}

// ---------------- helpers ----------------------------------------------------
__device__ __forceinline__ uint32_t pack_h2(float lo, float hi) {
    __half2 h = __floats2half2_rn(lo, hi);
    return *(uint32_t*)&h;
}

__device__ __forceinline__ void mma_f16(float& c0, float& c1, float& c2, float& c3,
                                        uint32_t a0, uint32_t a1, uint32_t a2, uint32_t a3,
                                        uint32_t b0, uint32_t b1) {
    asm volatile(
        "mma.sync.aligned.m16n8k16.row.col.f32.f16.f16.f32 "
        "{%0,%1,%2,%3}, {%4,%5,%6,%7}, {%8,%9}, {%0,%1,%2,%3};\n"
        : "+f"(c0), "+f"(c1), "+f"(c2), "+f"(c3)
        : "r"(a0), "r"(a1), "r"(a2), "r"(a3), "r"(b0), "r"(b1));
}

__device__ __forceinline__ unsigned bar_ld_acquire(const unsigned* p) {
    unsigned v;
    asm volatile("ld.global.acquire.gpu.u32 %0, [%1];" : "=r"(v) : "l"(p) : "memory");
    return v;
}
__device__ __forceinline__ void bar_red_release(unsigned* p, unsigned v) {
    asm volatile("red.release.gpu.global.add.u32 [%0], %1;" :: "l"(p), "r"(v) : "memory");
}

// ---------------- big GEMM (fp16 tensor cores): g_Xp = X @ Wx + b ------------
// 128x128 output tile per block, BK=32 (2 chunks of K=16 per buffered tile,
// halves the sync count vs BK=16). 256 threads = 8 warps (2x4 warp grid),
// each warp 64x32 via 4x4 m16n8k16 fragments. Smem: packed half2 with k-pair
// layout pos(j) = 8*chunk + 2*(j&3) + (j>>2); row stride 18 (== 18 mod 32,
// 2-way worst-case banks).
__global__ __launch_bounds__(256)
void xproj_f16_kernel(const float* __restrict__ X,
                      const float* __restrict__ W0, const float* __restrict__ W1,
                      const float* __restrict__ W2, const float* __restrict__ W3,
                      const float* __restrict__ b0, const float* __restrict__ b1,
                      const float* __restrict__ b2, const float* __restrict__ b3) {
    const int bn = blockIdx.x * 128;
    const int bm = blockIdx.y * 128;
    const int gate = bn >> 10;
    const float* W  = (gate == 0) ? W0 : (gate == 1) ? W1 : (gate == 2) ? W2 : W3;
    const float* bb = (gate == 0) ? b0 : (gate == 1) ? b1 : (gate == 2) ? b2 : b3;
    const int col0 = bn & (HID - 1);

    __shared__ uint32_t As[2][128][18];   // [m][16 k-pair slots, pad 18]
    __shared__ uint32_t Bs[2][128][18];   // [n][16 k-pair slots, pad 18]

    const int tid  = threadIdx.x;
    const int lane = tid & 31;
    const int warp = tid >> 5;
    const int wm   = warp >> 2;          // m offset wm*64
    const int wn   = warp & 3;           // n offset wn*32
    const int qg   = lane >> 2;
    const int qk   = lane & 3;

    // A loader: row ar, chunk ca (16 consecutive k = 4 float4 = 8 half2)
    const int ar = tid >> 1;             // 0..127
    const int ca = tid & 1;              // chunk 0/1, k base 16*ca
    // B loader: col bc, chunk cb (8 half2 = 16 k rows)
    const int bc = tid & 127;
    const int cb = tid >> 7;             // 0/1

    float c[4][4][4];
    #pragma unroll
    for (int mt = 0; mt < 4; mt++)
        #pragma unroll
        for (int nt = 0; nt < 4; nt++)
            #pragma unroll
            for (int r = 0; r < 4; r++) c[mt][nt][r] = 0.0f;

    // pos within chunk for half2 index j (0..7): 2*(j&3) + (j>>2)
    // float4 i (0..3) covers j = 2i, 2i+1.

    // ---- preload k-tile 0 ----
    {
        #pragma unroll
        for (int i = 0; i < 4; i++) {
            float4 av = *(const float4*)&X[(size_t)(bm + ar) * DIM + 16 * ca + 4 * i];
            const int j0 = 2 * i, j1 = 2 * i + 1;
            As[0][ar][8 * ca + 2 * (j0 & 3) + (j0 >> 2)] = pack_h2(av.x, av.y);
            As[0][ar][8 * ca + 2 * (j1 & 3) + (j1 >> 2)] = pack_h2(av.z, av.w);
        }
        #pragma unroll
        for (int j = 0; j < 8; j++) {
            const int kr = 16 * cb + 2 * j;
            float lo = W[(size_t)kr       * HID + col0 + bc];
            float hi = W[(size_t)(kr + 1) * HID + col0 + bc];
            Bs[0][bc][8 * cb + 2 * (j & 3) + (j >> 2)] = pack_h2(lo, hi);
        }
    }
    __syncthreads();

    int buf = 0;
    for (int kt = 0; kt < DIM / 32; kt++) {
        float4 av[4];
        float blo[8], bhi[8];
        const int k0n = (kt + 1) * 32;
        const bool has_next = (kt + 1 < DIM / 32);
        if (has_next) {
            #pragma unroll
            for (int i = 0; i < 4; i++)
                av[i] = *(const float4*)&X[(size_t)(bm + ar) * DIM + k0n + 16 * ca + 4 * i];
            #pragma unroll
            for (int j = 0; j < 8; j++) {
                const int kr = k0n + 16 * cb + 2 * j;
                blo[j] = W[(size_t)kr       * HID + col0 + bc];
                bhi[j] = W[(size_t)(kr + 1) * HID + col0 + bc];
            }
        }

        // ---- compute on current buffer: two K=16 chunks ----
        #pragma unroll
        for (int ch = 0; ch < 2; ch++) {
            uint2 a0p[4], a1p[4];
            #pragma unroll
            for (int mt = 0; mt < 4; mt++) {
                const int m = wm * 64 + mt * 16;
                a0p[mt] = *(const uint2*)&As[buf][m + qg][8 * ch + 2 * qk];
                a1p[mt] = *(const uint2*)&As[buf][m + qg + 8][8 * ch + 2 * qk];
            }
            uint2 bp[4];
            #pragma unroll
            for (int nt = 0; nt < 4; nt++) {
                const int n = wn * 32 + nt * 8;
                bp[nt] = *(const uint2*)&Bs[buf][n + qg][8 * ch + 2 * qk];
            }
            #pragma unroll
            for (int mt = 0; mt < 4; mt++)
                #pragma unroll
                for (int nt = 0; nt < 4; nt++)
                    mma_f16(c[mt][nt][0], c[mt][nt][1], c[mt][nt][2], c[mt][nt][3],
                            a0p[mt].x, a1p[mt].x, a0p[mt].y, a1p[mt].y,
                            bp[nt].x, bp[nt].y);
        }

        if (has_next) {
            const int nb = buf ^ 1;
            #pragma unroll
            for (int i = 0; i < 4; i++) {
                const int j0 = 2 * i, j1 = 2 * i + 1;
                As[nb][ar][8 * ca + 2 * (j0 & 3) + (j0 >> 2)] = pack_h2(av[i].x, av[i].y);
                As[nb][ar][8 * ca + 2 * (j1 & 3) + (j1 >> 2)] = pack_h2(av[i].z, av[i].w);
            }
            #pragma unroll
            for (int j = 0; j < 8; j++)
                Bs[nb][bc][8 * cb + 2 * (j & 3) + (j >> 2)] = pack_h2(blo[j], bhi[j]);
            __syncthreads();
            buf = nb;
        }
    }

    // ---- epilogue: add bias, store to g_Xp ----
    #pragma unroll
    for (int mt = 0; mt < 4; mt++) {
        #pragma unroll
        for (int nt = 0; nt < 4; nt++) {
            const int colg = wn * 32 + nt * 8 + 2 * qk;
            const float bx0 = bb[col0 + colg];
            const float bx1 = bb[col0 + colg + 1];
            const size_t row0 = (size_t)(bm + wm * 64 + mt * 16 + qg);
            float2 v0 = make_float2(c[mt][nt][0] + bx0, c[mt][nt][1] + bx1);
            float2 v1 = make_float2(c[mt][nt][2] + bx0, c[mt][nt][3] + bx1);
            *(float2*)&g_Xp[row0 * N4 + bn + colg]       = v0;
            *(float2*)&g_Xp[(row0 + 8) * N4 + bn + colg] = v1;
        }
    }
}

// ---------------- persistent recurrence kernel (fp16 m16n8k16) ---------------
// R15 structure with K-tile 64 per K-group (8 mainloop tiles, 8 syncs/step
// instead of 16). As row stride 50 (== 18 mod 32, proven conflict class).
//
// Wp[kc16=64][qk=4][gc pad 35][slot 2]  (half2 words) : 71,680 B
// As[kg=2][buf=2][m=64][32 slots pad 50](half2 words) : 102,400 B
// sg[kg=2][row=64][gc pad 33]           (float)       : 16,896 B   = 190,976 B
#define WP_WORDS (64 * 4 * 35 * 2)
#define AS_WORDS (2 * 2 * 64 * 50)
#define SG_WORDS (2 * 64 * 33)
#define SMEM_BYTES ((WP_WORDS + AS_WORDS + SG_WORDS) * 4)

__global__ __launch_bounds__(256)
void lstm_persistent(const float* __restrict__ W0, const float* __restrict__ W1,
                     const float* __restrict__ W2, const float* __restrict__ W3,
                     float* __restrict__ out) {
    extern __shared__ unsigned char smem_raw[];
    uint32_t (*Wp)[4][35][2]  = (uint32_t (*)[4][35][2])smem_raw;
    uint32_t (*As)[2][64][50] = (uint32_t (*)[2][64][50])(smem_raw + WP_WORDS * 4);
    float    (*sg)[64][33]    = (float (*)[64][33])(smem_raw + (WP_WORDS + AS_WORDS) * 4);

    const int tid  = threadIdx.x;
    const int lane = tid & 31;
    const int warp = tid >> 5;           // 0..7
    const int colbase = blockIdx.x * 8;

    const float* Wg[4] = {W0, W1, W2, W3};

    const int kg = warp >> 2;            // K-group 0/1
    const int wq = warp & 3;
    const int wm = wq >> 1;              // rows 32*wm
    const int wn = wq & 1;               // gate-cols 16*wn
    const int qg = lane >> 2;
    const int qk = lane & 3;

    // H loader mapping (128 threads per K-group), K-tile = 64 fp32 = 32 half2
    const int gtid = tid & 127;
    const int k2 = gtid & 31;            // half2 lane within tile (0..31)
    const int rh = gtid >> 5;            // row base 0..3, rows rh + 4i
    // paired store position for half2 index k2: ch = k2>>3, w = k2&7
    const int apos = ((k2 >> 3) << 3) | ((k2 & 3) << 1) | ((k2 >> 2) & 1);

    // epilogue mapping: 2 adjacent cells per thread
    const int erow = tid >> 2;           // 0..63
    const int ecc  = (tid & 3) * 2;      // 0,2,4,6
    const size_t xpb = (size_t)erow * N4 + colbase + ecc;

    // ---- load resident W (once) as half2 pairs ----
    {
        const int gc  = tid & 31;
        const int g   = gc >> 3;
        const int cl  = gc & 7;
        const int khb = (tid >> 5) * 64;
        for (int j = 0; j < 64; j++) {
            const int kh = khb + j;
            const int k  = kh * 2;
            const float lo = Wg[g][(size_t)k * HID + colbase + cl];
            const float hi = Wg[g][(size_t)(k + 1) * HID + colbase + cl];
            const int kc16 = kh >> 3;
            const int win  = kh & 7;
            Wp[kc16][win & 3][gc][win >> 2] = pack_h2(lo, hi);
        }
    }
    __syncthreads();

    // ---- prefetch Xp for step 0 ----
    float2 xp[4];
    #pragma unroll
    for (int g = 0; g < 4; g++)
        xp[g] = *(const float2*)&g_Xp[xpb + (size_t)g * HID];

    for (int t = 0; t < T_STEPS; t++) {
        float* Hout = out + (size_t)t * BATCH * HID;

        float c[2][2][4];
        #pragma unroll
        for (int mt = 0; mt < 2; mt++)
            #pragma unroll
            for (int nt = 0; nt < 2; nt++)
                #pragma unroll
                for (int r = 0; r < 4; r++) c[mt][nt][r] = 0.0f;

        const int khbase = kg * 256;     // this half's half2-K origin

        // preload H k-tile 0 (raw u32 half2 from g_Hh): 16 rows per thread
        #pragma unroll
        for (int i = 0; i < 16; i++) {
            const int row = rh + 4 * i;
            As[kg][0][row][apos] = __ldcg(&g_Hh[row * 512 + khbase + k2]);
        }
        __syncthreads();

        int buf = 0;
        for (int kt = 0; kt < 8; kt++) {
            uint32_t hreg[16];
            const bool has_next = (kt + 1 < 8);
            if (has_next) {
                const int kh0 = khbase + (kt + 1) * 32;
                #pragma unroll
                for (int i = 0; i < 16; i++)
                    hreg[i] = __ldcg(&g_Hh[(rh + 4 * i) * 512 + kh0 + k2]);
            }

            // compute on buf: 4 chunks of K=16
            #pragma unroll
            for (int ch = 0; ch < 4; ch++) {
                const int kc16 = kg * 32 + kt * 4 + ch;
                uint2 a01[2], a23[2];
                #pragma unroll
                for (int mt = 0; mt < 2; mt++) {
                    const int m = 32 * wm + 16 * mt;
                    a01[mt] = *(const uint2*)&As[kg][buf][m + qg][ch * 8 + 2 * qk];
                    a23[mt] = *(const uint2*)&As[kg][buf][m + qg + 8][ch * 8 + 2 * qk];
                }
                uint2 bp[2];
                #pragma unroll
                for (int nt = 0; nt < 2; nt++) {
                    const int n = 16 * wn + 8 * nt;
                    bp[nt] = *(const uint2*)&Wp[kc16][qk][n + qg][0];
                }
                #pragma unroll
                for (int mt = 0; mt < 2; mt++)
                    #pragma unroll
                    for (int nt = 0; nt < 2; nt++)
                        mma_f16(c[mt][nt][0], c[mt][nt][1], c[mt][nt][2], c[mt][nt][3],
                                a01[mt].x, a23[mt].x, a01[mt].y, a23[mt].y,
                                bp[nt].x, bp[nt].y);
            }

            if (has_next) {
                const int nb = buf ^ 1;
                #pragma unroll
                for (int i = 0; i < 16; i++)
                    As[kg][nb][rh + 4 * i][apos] = hreg[i];
                __syncthreads();
                buf = nb;
            }
        }

        // stash per-K-group gate partials
        #pragma unroll
        for (int mt = 0; mt < 2; mt++) {
            #pragma unroll
            for (int nt = 0; nt < 2; nt++) {
                const int row = 32 * wm + 16 * mt + qg;
                const int cn  = 16 * wn + 8 * nt + 2 * qk;
                sg[kg][row][cn]         = c[mt][nt][0];
                sg[kg][row][cn + 1]     = c[mt][nt][1];
                sg[kg][row + 8][cn]     = c[mt][nt][2];
                sg[kg][row + 8][cn + 1] = c[mt][nt][3];
            }
        }
        __syncthreads();

        // ---- fused LSTM cell epilogue: 2 adjacent cells per thread ----
        {
            const int idx = erow * HID + colbase + ecc;
            float2 cprev = *(const float2*)&g_C[idx];
            float hv[2], cv[2];
            #pragma unroll
            for (int s = 0; s < 2; s++) {
                const int cc = ecc + s;
                float gi = sg[0][erow][0  + cc] + sg[1][erow][0  + cc] + (s ? xp[0].y : xp[0].x);
                float gf = sg[0][erow][8  + cc] + sg[1][erow][8  + cc] + (s ? xp[1].y : xp[1].x);
                float go = sg[0][erow][16 + cc] + sg[1][erow][16 + cc] + (s ? xp[2].y : xp[2].x);
                float gg = sg[0][erow][24 + cc] + sg[1][erow][24 + cc] + (s ? xp[3].y : xp[3].x);

                float I = 1.0f / (1.0f + __expf(-gi));
                float F = 1.0f / (1.0f + __expf(-gf));
                float O = 1.0f / (1.0f + __expf(-go));
                float G = tanhf(gg);

                cv[s] = fmaf(F, (s ? cprev.y : cprev.x), I * G);
                hv[s] = O * tanhf(cv[s]);
            }
            *(float2*)&g_C[idx] = make_float2(cv[0], cv[1]);
            __stcg((float2*)&Hout[idx], make_float2(hv[0], hv[1]));
            __stcg(&g_Hh[erow * 512 + ((colbase + ecc) >> 1)], pack_h2(hv[0], hv[1]));
        }

        // ---- prefetch next step's Xp (read-only; overlaps barrier wait) ----
        if (t + 1 < T_STEPS) {
            const float* Xp_n = g_Xp + (size_t)(t + 1) * BATCH * N4;
            #pragma unroll
            for (int g = 0; g < 4; g++)
                xp[g] = *(const float2*)&Xp_n[xpb + (size_t)g * HID];
        }

        // ---- grid barrier (canonical CG pattern; causality via bar.sync) ----
        __syncthreads();
        if (tid == 0) {
            bar_red_release(&g_bar, 1u);
            const unsigned target = (unsigned)NBLK * (unsigned)(t + 1);
            while (bar_ld_acquire(&g_bar) < target) {}
        }
        __syncthreads();
    }
}

// ---------------- tail: H_f and C_f after outputs ---------------------------
__global__ void finalize_kernel(float* __restrict__ out) {
    int i = blockIdx.x * 256 + threadIdx.x;
    if (i < BATCH * HID) {
        size_t base = (size_t)T_STEPS * BATCH * HID;
        out[base + i] = out[(size_t)(T_STEPS - 1) * BATCH * HID + i];  // H_f
        out[base + BATCH * HID + i] = g_C[i];                          // C_f
    }
}

// ---------------- launch -----------------------------------------------------
extern "C" void kernel_launch(void* const* d_in, const int* in_sizes, int n_in,
                              void* d_out, int out_size) {
    const float* X   = (const float*)d_in[0];
    const float* H0  = (const float*)d_in[1];
    const float* C0  = (const float*)d_in[2];
    const float* Wxi = (const float*)d_in[3];
    const float* Wxf = (const float*)d_in[4];
    const float* Wxo = (const float*)d_in[5];
    const float* Wxc = (const float*)d_in[6];
    const float* Whi = (const float*)d_in[7];
    const float* Whf = (const float*)d_in[8];
    const float* Who = (const float*)d_in[9];
    const float* Whc = (const float*)d_in[10];
    const float* bi  = (const float*)d_in[11];
    const float* bf  = (const float*)d_in[12];
    const float* bo  = (const float*)d_in[13];
    const float* bc  = (const float*)d_in[14];
    float* out = (float*)d_out;

    cudaFuncSetAttribute(lstm_persistent,
                         cudaFuncAttributeMaxDynamicSharedMemorySize, SMEM_BYTES);

    init_c_kernel<<<256, 256>>>(C0, H0);
    xproj_f16_kernel<<<dim3(32, 256), 256>>>(X, Wxi, Wxf, Wxo, Wxc,
                                             bi, bf, bo, bc);
    lstm_persistent<<<NBLK, 256, SMEM_BYTES>>>(Whi, Whf, Who, Whc, out);
    finalize_kernel<<<256, 256>>>(out);
}